// round 1
// baseline (speedup 1.0000x reference)
#include <cuda_runtime.h>
#include <math.h>

// ---------------- problem constants ----------------
constexpr int B_  = 64;
constexpr int N_  = 257;
constexpr int C_  = 768;
constexpr int H_  = 12;
constexpr int D_  = 64;           // C_/H_
constexpr int HID_ = 3072;
constexpr int M_  = B_ * N_;      // 16448 rows
constexpr int C3_ = 3 * C_;       // 2304

constexpr size_t SZ_BNC  = (size_t)M_ * C_;        // 12,632,064
constexpr size_t SZ_QKV  = (size_t)M_ * C3_;       // 37,896,192
constexpr size_t SZ_ATT  = (size_t)B_ * H_ * N_ * N_; // 50,725,632
constexpr size_t SZ_HID  = (size_t)M_ * HID_;      // 50,528,256
constexpr size_t SZ_ASUM = (size_t)B_ * N_ * N_;   // 4,227,136

// ---------------- device scratch (static, no allocs) ----------------
__device__ float g_s   [SZ_BNC];
__device__ float g_t   [SZ_BNC];
__device__ float g_ln  [SZ_BNC];
__device__ float g_q1  [SZ_QKV];
__device__ float g_q2  [SZ_QKV];
__device__ float g_att [SZ_ATT];
__device__ float g_o   [SZ_BNC];
__device__ float g_sc  [SZ_BNC];
__device__ float g_hid [SZ_HID];
__device__ float g_tmp [SZ_BNC];
__device__ float g_asum[SZ_ASUM];
__device__ float g_heat[(size_t)B_ * N_];

// ---------------- elementwise kernels ----------------
__global__ void k_init(const float* __restrict__ src, const float* __restrict__ tgt,
                       const float* __restrict__ pos, float* __restrict__ s,
                       float* __restrict__ t) {
    size_t i = (size_t)blockIdx.x * blockDim.x + threadIdx.x;
    if (i >= SZ_BNC) return;
    size_t nc = i % ((size_t)N_ * C_);
    s[i] = src[i] + pos[nc];
    t[i] = tgt[i];
}

__global__ void k_add_inplace(float* __restrict__ y, const float* __restrict__ x, size_t n) {
    size_t i = (size_t)blockIdx.x * blockDim.x + threadIdx.x;
    if (i < n) y[i] += x[i];
}

__global__ void k_add_out(const float* __restrict__ a, const float* __restrict__ b,
                          float* __restrict__ out, size_t n) {
    size_t i = (size_t)blockIdx.x * blockDim.x + threadIdx.x;
    if (i < n) out[i] = a[i] + b[i];
}

__global__ void k_arf(float* __restrict__ x, size_t n) {
    size_t i = (size_t)blockIdx.x * blockDim.x + threadIdx.x;
    if (i >= n) return;
    float v = x[i];
    float ep = expf(v), en = expf(-v), en4 = expf(-v - 4.0f);
    float tmp = (ep - en) / (ep + en4);
    x[i] = tmp < 0.0f ? 0.0f : tmp;
}

// ---------------- layernorm: one block (256 thr) per row ----------------
__global__ void k_ln(const float* __restrict__ x, const float* __restrict__ g,
                     const float* __restrict__ b, float* __restrict__ y) {
    int row = blockIdx.x;
    int tid = threadIdx.x;
    const float* xr = x + (size_t)row * C_;
    float s = 0.f, q = 0.f;
    for (int i = tid; i < C_; i += 256) { float v = xr[i]; s += v; q += v * v; }
    __shared__ float rs[256], rq[256];
    rs[tid] = s; rq[tid] = q; __syncthreads();
    for (int o = 128; o > 0; o >>= 1) {
        if (tid < o) { rs[tid] += rs[tid + o]; rq[tid] += rq[tid + o]; }
        __syncthreads();
    }
    float mean = rs[0] * (1.0f / C_);
    float var  = rq[0] * (1.0f / C_) - mean * mean;
    float inv  = rsqrtf(var + 1e-5f);
    float* yr = y + (size_t)row * C_;
    for (int i = tid; i < C_; i += 256)
        yr[i] = (xr[i] - mean) * inv * g[i] + b[i];
}

// ---------------- NT SGEMM: C[m,n] = sum_k A[m,k] * W[n,k] (+bias)(+gelu) ----------------
// BM=BN=128, BK=8, 256 threads, 8x8 per thread
template<int ACT>
__global__ __launch_bounds__(256)
void gemm_nt(const float* __restrict__ A, const float* __restrict__ W,
             const float* __restrict__ bias, float* __restrict__ Cmat,
             int M, int Nn, int K) {
    __shared__ float As[8][128];
    __shared__ float Bs[8][128];
    const int bm = blockIdx.y * 128;
    const int bn = blockIdx.x * 128;
    const int tid = threadIdx.x;
    const int lr = tid >> 1;          // 0..127
    const int lk = (tid & 1) << 2;    // 0 or 4
    const int tm = (tid >> 4) << 3;   // 0..120 step 8
    const int tn = (tid & 15) << 3;

    float acc[8][8];
#pragma unroll
    for (int i = 0; i < 8; i++)
#pragma unroll
        for (int j = 0; j < 8; j++) acc[i][j] = 0.f;

    const bool a_ok = (bm + lr) < M;
    const bool b_ok = (bn + lr) < Nn;
    const float* Aptr = A + (size_t)(bm + lr) * K + lk;
    const float* Wptr = W + (size_t)(bn + lr) * K + lk;

    for (int k0 = 0; k0 < K; k0 += 8) {
        float4 av = a_ok ? *(const float4*)(Aptr + k0) : make_float4(0, 0, 0, 0);
        float4 bv = b_ok ? *(const float4*)(Wptr + k0) : make_float4(0, 0, 0, 0);
        __syncthreads();
        As[lk + 0][lr] = av.x; As[lk + 1][lr] = av.y;
        As[lk + 2][lr] = av.z; As[lk + 3][lr] = av.w;
        Bs[lk + 0][lr] = bv.x; Bs[lk + 1][lr] = bv.y;
        Bs[lk + 2][lr] = bv.z; Bs[lk + 3][lr] = bv.w;
        __syncthreads();
#pragma unroll
        for (int kk = 0; kk < 8; kk++) {
            float a[8], b[8];
#pragma unroll
            for (int i = 0; i < 8; i++) a[i] = As[kk][tm + i];
#pragma unroll
            for (int j = 0; j < 8; j++) b[j] = Bs[kk][tn + j];
#pragma unroll
            for (int i = 0; i < 8; i++)
#pragma unroll
                for (int j = 0; j < 8; j++) acc[i][j] = fmaf(a[i], b[j], acc[i][j]);
        }
    }

#pragma unroll
    for (int i = 0; i < 8; i++) {
        int row = bm + tm + i;
        if (row >= M) continue;
#pragma unroll
        for (int j = 0; j < 8; j++) {
            int col = bn + tn + j;
            if (col >= Nn) continue;
            float v = acc[i][j];
            if (bias) v += bias[col];
            if (ACT == 1) v = 0.5f * v * (1.0f + erff(v * 0.70710678118654752f));
            Cmat[(size_t)row * Nn + col] = v;
        }
    }
}

// ---------------- attention scores: S[n,m] = 0.125 * q_n . k_m ----------------
__global__ void k_scores(const float* __restrict__ qsrc, const float* __restrict__ ksrc,
                         float* __restrict__ attn) {
    int bh = blockIdx.z;
    int b = bh / H_, h = bh % H_;
    const float* qb = qsrc + (size_t)b * N_ * C3_ + h * D_;        // q[n,d]: +n*C3_
    const float* kb = ksrc + (size_t)b * N_ * C3_ + C_ + h * D_;   // k[m,d]
    __shared__ float Qs[32][D_ + 1];
    __shared__ float Ks[32][D_ + 1];
    int n0 = blockIdx.y * 32, m0 = blockIdx.x * 32;
    int tid = threadIdx.x;
    for (int e = tid; e < 32 * D_; e += 256) {
        int r = e >> 6, c = e & 63;
        Qs[r][c] = (n0 + r < N_) ? qb[(size_t)(n0 + r) * C3_ + c] : 0.f;
        Ks[r][c] = (m0 + r < N_) ? kb[(size_t)(m0 + r) * C3_ + c] : 0.f;
    }
    __syncthreads();
    int tx = tid & 31, ty = tid >> 5;  // tx: m-lane, ty: 0..7
    float acc[4] = {0.f, 0.f, 0.f, 0.f};
    for (int d = 0; d < D_; d++) {
        float kv = Ks[tx][d];
#pragma unroll
        for (int r = 0; r < 4; r++) acc[r] = fmaf(Qs[ty + 8 * r][d], kv, acc[r]);
    }
    int m = m0 + tx;
    if (m < N_) {
        float* arow = attn + (size_t)bh * N_ * N_;
#pragma unroll
        for (int r = 0; r < 4; r++) {
            int n = n0 + ty + 8 * r;
            if (n < N_) arow[(size_t)n * N_ + m] = acc[r] * 0.125f;
        }
    }
}

// ---------------- row softmax (length N_) ----------------
__global__ void k_softmax(float* __restrict__ attn) {
    size_t row = blockIdx.x;
    float* p = attn + row * (size_t)N_;
    int tid = threadIdx.x;  // 128
    __shared__ float red[128];
    float m = -1e30f;
    for (int i = tid; i < N_; i += 128) m = fmaxf(m, p[i]);
    red[tid] = m; __syncthreads();
    for (int o = 64; o > 0; o >>= 1) {
        if (tid < o) red[tid] = fmaxf(red[tid], red[tid + o]);
        __syncthreads();
    }
    m = red[0]; __syncthreads();
    float s = 0.f;
    for (int i = tid; i < N_; i += 128) { float e = expf(p[i] - m); p[i] = e; s += e; }
    red[tid] = s; __syncthreads();
    for (int o = 64; o > 0; o >>= 1) {
        if (tid < o) red[tid] += red[tid + o];
        __syncthreads();
    }
    float inv = 1.0f / red[0];
    for (int i = tid; i < N_; i += 128) p[i] *= inv;
}

// ---------------- O[b,n,h*D+d] = sum_m P[n,m] V[m,d] ----------------
__global__ void k_av(const float* __restrict__ attn, const float* __restrict__ vsrc,
                     float* __restrict__ o) {
    int bh = blockIdx.y;
    int b = bh / H_, h = bh % H_;
    int idx = blockIdx.x * 256 + threadIdx.x;
    if (idx >= N_ * D_) return;
    int n = idx >> 6, d = idx & 63;
    const float* P = attn + (size_t)bh * N_ * N_ + (size_t)n * N_;
    const float* V = vsrc + (size_t)b * N_ * C3_ + 2 * C_ + h * D_ + d;
    float s = 0.f;
    for (int m = 0; m < N_; m++) s = fmaf(P[m], V[(size_t)m * C3_], s);
    o[((size_t)(b * N_ + n)) * C_ + h * D_ + d] = s;
}

// ---------------- head sum: asum[b,n,m] = sum_h attn[b,h,n,m] ----------------
__global__ void k_headsum(const float* __restrict__ attn, float* __restrict__ asum) {
    size_t idx = (size_t)blockIdx.x * 256 + threadIdx.x;
    if (idx >= SZ_ASUM) return;
    size_t b = idx / ((size_t)N_ * N_);
    size_t r = idx % ((size_t)N_ * N_);
    float s = 0.f;
    for (int h = 0; h < H_; h++) s += attn[((size_t)(b * H_ + h)) * N_ * N_ + r];
    asum[idx] = s;
}

// ---------------- heat[b,m] = mean_n asum[b,n,m] ----------------
__global__ void k_heat(const float* __restrict__ asum, float* __restrict__ heat) {
    int idx = blockIdx.x * 256 + threadIdx.x;
    if (idx >= B_ * N_) return;
    int b = idx / N_, m = idx % N_;
    const float* p = asum + (size_t)b * N_ * N_ + m;
    float s = 0.f;
    for (int n = 0; n < N_; n++) s += p[(size_t)n * N_];
    heat[idx] = s * (1.0f / N_);
}

// ---------------- tgt output: t + t * saw[c] * sigmoid(heat[b,n]) ----------------
__global__ void k_tgt_out(const float* __restrict__ t, const float* __restrict__ saw,
                          const float* __restrict__ heat, float* __restrict__ out) {
    size_t i = (size_t)blockIdx.x * 256 + threadIdx.x;
    if (i >= SZ_BNC) return;
    int row = (int)(i / C_);
    int c   = (int)(i % C_);
    float gate = 1.0f / (1.0f + expf(-heat[row]));
    float tv = t[i];
    out[i] = tv + tv * saw[c] * gate;
}

// ---------------- attm copy: out[b,i,j] = asum[b,i+1,j+1] ----------------
__global__ void k_attm(const float* __restrict__ asum, float* __restrict__ out) {
    size_t idx = (size_t)blockIdx.x * 256 + threadIdx.x;
    size_t total = (size_t)B_ * 256 * 256;
    if (idx >= total) return;
    size_t b = idx / 65536;
    size_t r = idx % 65536;
    int i = (int)(r >> 8), j = (int)(r & 255);
    out[idx] = asum[(size_t)b * N_ * N_ + (size_t)(i + 1) * N_ + (j + 1)];
}

// ---------------- host orchestration ----------------
static inline dim3 gemm_grid(int M, int Nn) {
    return dim3((Nn + 127) / 128, (M + 127) / 128);
}

extern "C" void kernel_launch(void* const* d_in, const int* in_sizes, int n_in,
                              void* d_out, int out_size) {
    const float* in_src   = (const float*)d_in[0];
    const float* in_tgt   = (const float*)d_in[1];
    const float* sattn_qkv_w  = (const float*)d_in[2];
    const float* sattn_proj_w = (const float*)d_in[3];
    const float* sattn_proj_b = (const float*)d_in[4];
    const float* cattn_qkv_w  = (const float*)d_in[5];
    const float* cattn_proj_w = (const float*)d_in[6];
    const float* cattn_proj_b = (const float*)d_in[7];
    const float* n1g = (const float*)d_in[8];
    const float* n1b = (const float*)d_in[9];
    const float* n2g = (const float*)d_in[10];
    const float* n2b = (const float*)d_in[11];
    const float* fc1_w = (const float*)d_in[12];
    const float* fc1_b = (const float*)d_in[13];
    const float* fc2_w = (const float*)d_in[14];
    const float* fc2_b = (const float*)d_in[15];
    const float* saw   = (const float*)d_in[16];
    const float* pos   = (const float*)d_in[17];

    float *s, *t, *ln, *q1, *q2, *at, *ob, *sc, *hd, *tp, *as_, *ht;
    cudaGetSymbolAddress((void**)&s,   g_s);
    cudaGetSymbolAddress((void**)&t,   g_t);
    cudaGetSymbolAddress((void**)&ln,  g_ln);
    cudaGetSymbolAddress((void**)&q1,  g_q1);
    cudaGetSymbolAddress((void**)&q2,  g_q2);
    cudaGetSymbolAddress((void**)&at,  g_att);
    cudaGetSymbolAddress((void**)&ob,  g_o);
    cudaGetSymbolAddress((void**)&sc,  g_sc);
    cudaGetSymbolAddress((void**)&hd,  g_hid);
    cudaGetSymbolAddress((void**)&tp,  g_tmp);
    cudaGetSymbolAddress((void**)&as_, g_asum);
    cudaGetSymbolAddress((void**)&ht,  g_heat);

    float* out_src  = (float*)d_out;
    float* out_tgt  = out_src + SZ_BNC;
    float* out_attm = out_tgt + SZ_BNC;

    const int EW = (int)((SZ_BNC + 255) / 256);
    dim3 sc_grid(9, 9, B_ * H_);             // score tiles
    int  av_gx = (N_ * D_ + 255) / 256;      // 65
    dim3 av_grid(av_gx, B_ * H_);
    int  sm_rows = B_ * H_ * N_;

    // ---- src = src + pos; t = tgt ----
    k_init<<<EW, 256>>>(in_src, in_tgt, pos, s, t);

    // ---- self attention on src ----
    k_ln<<<M_, 256>>>(s, n1g, n1b, ln);
    gemm_nt<0><<<gemm_grid(M_, C3_), 256>>>(ln, sattn_qkv_w, nullptr, q1, M_, C3_, C_);
    k_scores<<<sc_grid, 256>>>(q1, q1, at);
    k_softmax<<<sm_rows, 128>>>(at);
    k_av<<<av_grid, 256>>>(at, q1, ob);
    gemm_nt<0><<<gemm_grid(M_, C_), 256>>>(ob, sattn_proj_w, sattn_proj_b, sc, M_, C_, C_);
    k_add_inplace<<<EW, 256>>>(s, sc, SZ_BNC);      // src += srct
    // mlp(ln2(srct))
    k_ln<<<M_, 256>>>(sc, n2g, n2b, ln);
    gemm_nt<1><<<gemm_grid(M_, HID_), 256>>>(ln, fc1_w, fc1_b, hd, M_, HID_, C_);
    gemm_nt<0><<<gemm_grid(M_, C_), 256>>>(hd, fc2_w, fc2_b, tp, M_, C_, HID_);
    k_add_inplace<<<EW, 256>>>(s, tp, SZ_BNC);

    // ---- self attention on tgt ----
    k_ln<<<M_, 256>>>(t, n1g, n1b, ln);
    gemm_nt<0><<<gemm_grid(M_, C3_), 256>>>(ln, sattn_qkv_w, nullptr, q1, M_, C3_, C_);
    k_scores<<<sc_grid, 256>>>(q1, q1, at);
    k_softmax<<<sm_rows, 128>>>(at);
    k_av<<<av_grid, 256>>>(at, q1, ob);
    gemm_nt<0><<<gemm_grid(M_, C_), 256>>>(ob, sattn_proj_w, sattn_proj_b, sc, M_, C_, C_);
    k_add_inplace<<<EW, 256>>>(t, sc, SZ_BNC);      // tgt += tgtt
    k_ln<<<M_, 256>>>(sc, n2g, n2b, ln);
    gemm_nt<1><<<gemm_grid(M_, HID_), 256>>>(ln, fc1_w, fc1_b, hd, M_, HID_, C_);
    gemm_nt<0><<<gemm_grid(M_, C_), 256>>>(hd, fc2_w, fc2_b, tp, M_, C_, HID_);
    k_add_inplace<<<EW, 256>>>(t, tp, SZ_BNC);

    // ---- cross attention: q from ln(src), k/v from ln(tgt) ----
    k_ln<<<M_, 256>>>(s, n1g, n1b, ln);
    gemm_nt<0><<<gemm_grid(M_, C3_), 256>>>(ln, cattn_qkv_w, nullptr, q1, M_, C3_, C_);
    k_ln<<<M_, 256>>>(t, n1g, n1b, ln);
    gemm_nt<0><<<gemm_grid(M_, C3_), 256>>>(ln, cattn_qkv_w, nullptr, q2, M_, C3_, C_);
    k_scores<<<sc_grid, 256>>>(q1, q2, at);
    k_softmax<<<sm_rows, 128>>>(at);
    k_headsum<<<(int)((SZ_ASUM + 255) / 256), 256>>>(at, as_);
    k_av<<<av_grid, 256>>>(at, q2, ob);
    gemm_nt<0><<<gemm_grid(M_, C_), 256>>>(ob, cattn_proj_w, cattn_proj_b, sc, M_, C_, C_);
    k_arf<<<EW, 256>>>(sc, SZ_BNC);
    k_add_inplace<<<EW, 256>>>(s, sc, SZ_BNC);      // src += arf(srct)
    k_ln<<<M_, 256>>>(sc, n2g, n2b, ln);
    gemm_nt<1><<<gemm_grid(M_, HID_), 256>>>(ln, fc1_w, fc1_b, hd, M_, HID_, C_);
    gemm_nt<0><<<gemm_grid(M_, C_), 256>>>(hd, fc2_w, fc2_b, tp, M_, C_, HID_);
    k_add_out<<<EW, 256>>>(s, tp, out_src, SZ_BNC); // final src -> out

    // ---- gate + tgt out ----
    k_heat<<<(B_ * N_ + 255) / 256, 256>>>(as_, ht);
    k_tgt_out<<<EW, 256>>>(t, saw, ht, out_tgt);

    // ---- attm out ----
    k_attm<<<(int)(((size_t)B_ * 256 * 256 + 255) / 256), 256>>>(as_, out_attm);
}

// round 5
// speedup vs baseline: 1.8692x; 1.8692x over previous
#include <cuda_runtime.h>
#include <cuda_bf16.h>
#include <math.h>
#include <stdint.h>

// ---------------- problem constants ----------------
constexpr int B_  = 64;
constexpr int N_  = 257;
constexpr int C_  = 768;
constexpr int H_  = 12;
constexpr int D_  = 64;           // C_/H_
constexpr int HID_ = 3072;
constexpr int M_  = B_ * N_;      // 16448 rows
constexpr int C3_ = 3 * C_;       // 2304

constexpr size_t SZ_BNC  = (size_t)M_ * C_;
constexpr size_t SZ_QKV  = (size_t)M_ * C3_;
constexpr size_t SZ_ATT  = (size_t)B_ * H_ * N_ * N_;
constexpr size_t SZ_HID  = (size_t)M_ * HID_;
constexpr size_t SZ_ASUM = (size_t)B_ * N_ * N_;

// ---------------- device scratch (static, no allocs) ----------------
__device__ float g_s   [SZ_BNC];
__device__ float g_t   [SZ_BNC];
__device__ float g_ln  [SZ_BNC];
__device__ float g_q1  [SZ_QKV];
__device__ float g_q2  [SZ_QKV];
__device__ float g_att [SZ_ATT];
__device__ float g_o   [SZ_BNC];
__device__ float g_sc  [SZ_BNC];
__device__ float g_hid [SZ_HID];
__device__ float g_tmp [SZ_BNC];
__device__ float g_asum[SZ_ASUM];
__device__ float g_heat[(size_t)B_ * N_];

// ================= helpers =================
__device__ __forceinline__ uint32_t smem_u32(const void* p) {
    uint32_t a;
    asm("{ .reg .u64 t; cvta.to.shared.u64 t, %1; cvt.u32.u64 %0, t; }"
        : "=r"(a) : "l"(p));
    return a;
}

#define SW128(o) ((o) ^ (((o) >> 3) & 0x70))

#define LDSM_X4(r0, r1, r2, r3, addr) \
    asm volatile("ldmatrix.sync.aligned.m8n8.x4.shared.b16 {%0,%1,%2,%3}, [%4];" \
        : "=r"(r0), "=r"(r1), "=r"(r2), "=r"(r3) : "r"(addr))

#define LDSM_X2(r0, r1, addr) \
    asm volatile("ldmatrix.sync.aligned.m8n8.x2.shared.b16 {%0,%1}, [%2];" \
        : "=r"(r0), "=r"(r1) : "r"(addr))

#define MMA16816(d, a, b0, b1) \
    asm volatile("mma.sync.aligned.m16n8k16.row.col.f32.bf16.bf16.f32 " \
        "{%0,%1,%2,%3},{%4,%5,%6,%7},{%8,%9},{%0,%1,%2,%3};" \
        : "+f"((d)[0]), "+f"((d)[1]), "+f"((d)[2]), "+f"((d)[3]) \
        : "r"((a)[0]), "r"((a)[1]), "r"((a)[2]), "r"((a)[3]), "r"(b0), "r"(b1))

// split one fp32 x8 into hi/lo bf16x2 quads
__device__ __forceinline__ void cvt_hilo8(const float* x, uint4& hq, uint4& lq) {
    uint32_t hp[4], lp[4];
#pragma unroll
    for (int i = 0; i < 4; i++) {
        float a = x[2 * i], b = x[2 * i + 1];
        __nv_bfloat162 h2 = __float22bfloat162_rn(make_float2(a, b));
        uint32_t h = *(uint32_t*)&h2;
        hp[i] = h;
        float fa = __uint_as_float(h << 16);
        float fb = __uint_as_float(h & 0xFFFF0000u);
        __nv_bfloat162 l2 = __float22bfloat162_rn(make_float2(a - fa, b - fb));
        lp[i] = *(uint32_t*)&l2;
    }
    hq = make_uint4(hp[0], hp[1], hp[2], hp[3]);
    lq = make_uint4(lp[0], lp[1], lp[2], lp[3]);
}

// ================= split-bf16 mma.sync GEMM =================
// C[m,n] = sum_k A[m,k]*W[n,k] (+bias)(+gelu)
// 128x128 tiles, BK=32, 8 warps (4m x 2n), double-buffered smem.
constexpr uint32_t T_AH = 0;
constexpr uint32_t T_AL = 8192;
constexpr uint32_t T_BH = 16384;
constexpr uint32_t T_BL = 24576;
constexpr uint32_t STAGE = 32768;
constexpr int GEMM_SMEM = 65536;

template<int ACT>
__global__ __launch_bounds__(256, 1)
void gemm_mma(const float* __restrict__ A, const float* __restrict__ W,
              const float* __restrict__ bias, float* __restrict__ Cmat,
              int M, int Nn, int K) {
    extern __shared__ __align__(1024) char smem[];
    const uint32_t sb = smem_u32(smem);
    const int tid  = threadIdx.x;
    const int wid  = tid >> 5;
    const int lane = tid & 31;
    const int bm   = blockIdx.y * 128;
    const int bn   = blockIdx.x * 128;
    const int wm   = (wid & 3) * 32;   // warp row offset in tile
    const int wn   = (wid >> 2) * 64;  // warp col offset in tile

    // loader mapping: each thread owns one tile row, 16 consecutive k floats
    const int lr = tid >> 1;
    const int lk = (tid & 1) * 16;
    const bool aOk = (bm + lr) < M;
    const float* Ap = A + (size_t)(bm + lr) * K + lk;
    const float* Wp = W + (size_t)(bn + lr) * K + lk;

    float acc[2][8][4];
#pragma unroll
    for (int i = 0; i < 2; i++)
#pragma unroll
        for (int j = 0; j < 8; j++)
#pragma unroll
            for (int r = 0; r < 4; r++) acc[i][j][r] = 0.f;

    float ra[16], rb[16];

    // ---- prologue load (k0 = 0) ----
#pragma unroll
    for (int u = 0; u < 2; ++u) {
        if (aOk) {
            float4 v0 = *(const float4*)(Ap + u * 8);
            float4 v1 = *(const float4*)(Ap + u * 8 + 4);
            ra[u*8+0]=v0.x; ra[u*8+1]=v0.y; ra[u*8+2]=v0.z; ra[u*8+3]=v0.w;
            ra[u*8+4]=v1.x; ra[u*8+5]=v1.y; ra[u*8+6]=v1.z; ra[u*8+7]=v1.w;
        } else {
#pragma unroll
            for (int q = 0; q < 8; q++) ra[u*8+q] = 0.f;
        }
        float4 w0 = *(const float4*)(Wp + u * 8);
        float4 w1 = *(const float4*)(Wp + u * 8 + 4);
        rb[u*8+0]=w0.x; rb[u*8+1]=w0.y; rb[u*8+2]=w0.z; rb[u*8+3]=w0.w;
        rb[u*8+4]=w1.x; rb[u*8+5]=w1.y; rb[u*8+6]=w1.z; rb[u*8+7]=w1.w;
    }
    // store stage 0
    {
        const uint32_t soff = lr * 64u;
#pragma unroll
        for (int u = 0; u < 2; ++u) {
            uint32_t off = soff + (uint32_t)(lk + u * 8) * 2u;
            uint32_t sw = SW128(off);
            uint4 hq, lq;
            cvt_hilo8(&ra[u * 8], hq, lq);
            *(uint4*)(smem + T_AH + sw) = hq;
            *(uint4*)(smem + T_AL + sw) = lq;
            cvt_hilo8(&rb[u * 8], hq, lq);
            *(uint4*)(smem + T_BH + sw) = hq;
            *(uint4*)(smem + T_BL + sw) = lq;
        }
    }
    __syncthreads();

    const int nit = K >> 5;
    for (int it = 0; it < nit; ++it) {
        // ---- prefetch next chunk into registers ----
        if (it + 1 < nit) {
            const int k0 = (it + 1) << 5;
#pragma unroll
            for (int u = 0; u < 2; ++u) {
                if (aOk) {
                    float4 v0 = *(const float4*)(Ap + k0 + u * 8);
                    float4 v1 = *(const float4*)(Ap + k0 + u * 8 + 4);
                    ra[u*8+0]=v0.x; ra[u*8+1]=v0.y; ra[u*8+2]=v0.z; ra[u*8+3]=v0.w;
                    ra[u*8+4]=v1.x; ra[u*8+5]=v1.y; ra[u*8+6]=v1.z; ra[u*8+7]=v1.w;
                } else {
#pragma unroll
                    for (int q = 0; q < 8; q++) ra[u*8+q] = 0.f;
                }
                float4 w0 = *(const float4*)(Wp + k0 + u * 8);
                float4 w1 = *(const float4*)(Wp + k0 + u * 8 + 4);
                rb[u*8+0]=w0.x; rb[u*8+1]=w0.y; rb[u*8+2]=w0.z; rb[u*8+3]=w0.w;
                rb[u*8+4]=w1.x; rb[u*8+5]=w1.y; rb[u*8+6]=w1.z; rb[u*8+7]=w1.w;
            }
        }

        // ---- MMAs on current stage ----
        const uint32_t stb = sb + (uint32_t)(it & 1) * STAGE;
#pragma unroll
        for (int ks = 0; ks < 2; ++ks) {
            const int kk = ks * 16;
            uint32_t ah[2][4], al[2][4];
#pragma unroll
            for (int mt = 0; mt < 2; ++mt) {
                uint32_t off = (uint32_t)(wm + mt * 16 + (lane & 15)) * 64u
                             + (uint32_t)(kk + (lane >> 4) * 8) * 2u;
                uint32_t sw = SW128(off);
                LDSM_X4(ah[mt][0], ah[mt][1], ah[mt][2], ah[mt][3], stb + T_AH + sw);
                LDSM_X4(al[mt][0], al[mt][1], al[mt][2], al[mt][3], stb + T_AL + sw);
            }
#pragma unroll
            for (int nt = 0; nt < 8; ++nt) {
                const int l8 = lane & 15;
                uint32_t boff = (uint32_t)(wn + nt * 8 + (l8 & 7)) * 64u
                              + (uint32_t)(kk + ((l8 >> 3) & 1) * 8) * 2u;
                uint32_t bsw = SW128(boff);
                uint32_t b0, b1, c0, c1;
                LDSM_X2(b0, b1, stb + T_BH + bsw);
                LDSM_X2(c0, c1, stb + T_BL + bsw);
#pragma unroll
                for (int mt = 0; mt < 2; ++mt) {
                    MMA16816(acc[mt][nt], ah[mt], b0, b1);
                    MMA16816(acc[mt][nt], ah[mt], c0, c1);
                    MMA16816(acc[mt][nt], al[mt], b0, b1);
                }
            }
        }

        // ---- store next stage ----
        if (it + 1 < nit) {
            const uint32_t base = (uint32_t)((it + 1) & 1) * STAGE;
            const uint32_t soff = lr * 64u;
#pragma unroll
            for (int u = 0; u < 2; ++u) {
                uint32_t off = soff + (uint32_t)(lk + u * 8) * 2u;
                uint32_t sw = SW128(off);
                uint4 hq, lq;
                cvt_hilo8(&ra[u * 8], hq, lq);
                *(uint4*)(smem + base + T_AH + sw) = hq;
                *(uint4*)(smem + base + T_AL + sw) = lq;
                cvt_hilo8(&rb[u * 8], hq, lq);
                *(uint4*)(smem + base + T_BH + sw) = hq;
                *(uint4*)(smem + base + T_BL + sw) = lq;
            }
        }
        __syncthreads();
    }

    // ---- epilogue ----
#pragma unroll
    for (int mt = 0; mt < 2; ++mt) {
#pragma unroll
        for (int half = 0; half < 2; ++half) {
            const int row = bm + wm + mt * 16 + (lane >> 2) + half * 8;
            if (row < M) {
#pragma unroll
                for (int nt = 0; nt < 8; ++nt) {
                    const int col = bn + wn + nt * 8 + (lane & 3) * 2;
                    float v0 = acc[mt][nt][half * 2 + 0];
                    float v1 = acc[mt][nt][half * 2 + 1];
                    if (bias) { v0 += bias[col]; v1 += bias[col + 1]; }
                    if (ACT == 1) {
                        v0 = 0.5f * v0 * (1.0f + erff(v0 * 0.70710678118654752f));
                        v1 = 0.5f * v1 * (1.0f + erff(v1 * 0.70710678118654752f));
                    }
                    *(float2*)&Cmat[(size_t)row * Nn + col] = make_float2(v0, v1);
                }
            }
        }
    }
}

// ---------------- elementwise kernels ----------------
__global__ void k_init(const float* __restrict__ src, const float* __restrict__ tgt,
                       const float* __restrict__ pos, float* __restrict__ s,
                       float* __restrict__ t) {
    size_t i = (size_t)blockIdx.x * blockDim.x + threadIdx.x;
    if (i >= SZ_BNC) return;
    size_t nc = i % ((size_t)N_ * C_);
    s[i] = src[i] + pos[nc];
    t[i] = tgt[i];
}

__global__ void k_add_inplace(float* __restrict__ y, const float* __restrict__ x, size_t n) {
    size_t i = (size_t)blockIdx.x * blockDim.x + threadIdx.x;
    if (i < n) y[i] += x[i];
}

__global__ void k_add_out(const float* __restrict__ a, const float* __restrict__ b,
                          float* __restrict__ out, size_t n) {
    size_t i = (size_t)blockIdx.x * blockDim.x + threadIdx.x;
    if (i < n) out[i] = a[i] + b[i];
}

__global__ void k_arf(float* __restrict__ x, size_t n) {
    size_t i = (size_t)blockIdx.x * blockDim.x + threadIdx.x;
    if (i >= n) return;
    float v = x[i];
    float ep = expf(v), en = expf(-v), en4 = expf(-v - 4.0f);
    float tmp = (ep - en) / (ep + en4);
    x[i] = tmp < 0.0f ? 0.0f : tmp;
}

// ---------------- layernorm ----------------
__global__ void k_ln(const float* __restrict__ x, const float* __restrict__ g,
                     const float* __restrict__ b, float* __restrict__ y) {
    int row = blockIdx.x;
    int tid = threadIdx.x;
    const float* xr = x + (size_t)row * C_;
    float s = 0.f, q = 0.f;
    for (int i = tid; i < C_; i += 256) { float v = xr[i]; s += v; q += v * v; }
    __shared__ float rs[256], rq[256];
    rs[tid] = s; rq[tid] = q; __syncthreads();
    for (int o = 128; o > 0; o >>= 1) {
        if (tid < o) { rs[tid] += rs[tid + o]; rq[tid] += rq[tid + o]; }
        __syncthreads();
    }
    float mean = rs[0] * (1.0f / C_);
    float var  = rq[0] * (1.0f / C_) - mean * mean;
    float inv  = rsqrtf(var + 1e-5f);
    float* yr = y + (size_t)row * C_;
    for (int i = tid; i < C_; i += 256)
        yr[i] = (xr[i] - mean) * inv * g[i] + b[i];
}

// ---------------- attention scores ----------------
__global__ void k_scores(const float* __restrict__ qsrc, const float* __restrict__ ksrc,
                         float* __restrict__ attn) {
    int bh = blockIdx.z;
    int b = bh / H_, h = bh % H_;
    const float* qb = qsrc + (size_t)b * N_ * C3_ + h * D_;
    const float* kb = ksrc + (size_t)b * N_ * C3_ + C_ + h * D_;
    __shared__ float Qs[32][D_ + 1];
    __shared__ float Ks[32][D_ + 1];
    int n0 = blockIdx.y * 32, m0 = blockIdx.x * 32;
    int tid = threadIdx.x;
    for (int e = tid; e < 32 * D_; e += 256) {
        int r = e >> 6, c = e & 63;
        Qs[r][c] = (n0 + r < N_) ? qb[(size_t)(n0 + r) * C3_ + c] : 0.f;
        Ks[r][c] = (m0 + r < N_) ? kb[(size_t)(m0 + r) * C3_ + c] : 0.f;
    }
    __syncthreads();
    int tx = tid & 31, ty = tid >> 5;
    float acc[4] = {0.f, 0.f, 0.f, 0.f};
    for (int d = 0; d < D_; d++) {
        float kv = Ks[tx][d];
#pragma unroll
        for (int r = 0; r < 4; r++) acc[r] = fmaf(Qs[ty + 8 * r][d], kv, acc[r]);
    }
    int m = m0 + tx;
    if (m < N_) {
        float* arow = attn + (size_t)bh * N_ * N_;
#pragma unroll
        for (int r = 0; r < 4; r++) {
            int n = n0 + ty + 8 * r;
            if (n < N_) arow[(size_t)n * N_ + m] = acc[r] * 0.125f;
        }
    }
}

// ---------------- row softmax ----------------
__global__ void k_softmax(float* __restrict__ attn) {
    size_t row = blockIdx.x;
    float* p = attn + row * (size_t)N_;
    int tid = threadIdx.x;
    __shared__ float red[128];
    float m = -1e30f;
    for (int i = tid; i < N_; i += 128) m = fmaxf(m, p[i]);
    red[tid] = m; __syncthreads();
    for (int o = 64; o > 0; o >>= 1) {
        if (tid < o) red[tid] = fmaxf(red[tid], red[tid + o]);
        __syncthreads();
    }
    m = red[0]; __syncthreads();
    float s = 0.f;
    for (int i = tid; i < N_; i += 128) { float e = expf(p[i] - m); p[i] = e; s += e; }
    red[tid] = s; __syncthreads();
    for (int o = 64; o > 0; o >>= 1) {
        if (tid < o) red[tid] += red[tid + o];
        __syncthreads();
    }
    float inv = 1.0f / red[0];
    for (int i = tid; i < N_; i += 128) p[i] *= inv;
}

// ---------------- AV ----------------
__global__ void k_av(const float* __restrict__ attn, const float* __restrict__ vsrc,
                     float* __restrict__ o) {
    int bh = blockIdx.y;
    int b = bh / H_, h = bh % H_;
    int idx = blockIdx.x * 256 + threadIdx.x;
    if (idx >= N_ * D_) return;
    int n = idx >> 6, d = idx & 63;
    const float* P = attn + (size_t)bh * N_ * N_ + (size_t)n * N_;
    const float* V = vsrc + (size_t)b * N_ * C3_ + 2 * C_ + h * D_ + d;
    float s = 0.f;
    for (int m = 0; m < N_; m++) s = fmaf(P[m], V[(size_t)m * C3_], s);
    o[((size_t)(b * N_ + n)) * C_ + h * D_ + d] = s;
}

// ---------------- head sum ----------------
__global__ void k_headsum(const float* __restrict__ attn, float* __restrict__ asum) {
    size_t idx = (size_t)blockIdx.x * 256 + threadIdx.x;
    if (idx >= SZ_ASUM) return;
    size_t b = idx / ((size_t)N_ * N_);
    size_t r = idx % ((size_t)N_ * N_);
    float s = 0.f;
    for (int h = 0; h < H_; h++) s += attn[((size_t)(b * H_ + h)) * N_ * N_ + r];
    asum[idx] = s;
}

// ---------------- heat ----------------
__global__ void k_heat(const float* __restrict__ asum, float* __restrict__ heat) {
    int idx = blockIdx.x * 256 + threadIdx.x;
    if (idx >= B_ * N_) return;
    int b = idx / N_, m = idx % N_;
    const float* p = asum + (size_t)b * N_ * N_ + m;
    float s = 0.f;
    for (int n = 0; n < N_; n++) s += p[(size_t)n * N_];
    heat[idx] = s * (1.0f / N_);
}

// ---------------- tgt output ----------------
__global__ void k_tgt_out(const float* __restrict__ t, const float* __restrict__ saw,
                          const float* __restrict__ heat, float* __restrict__ out) {
    size_t i = (size_t)blockIdx.x * 256 + threadIdx.x;
    if (i >= SZ_BNC) return;
    int row = (int)(i / C_);
    int c   = (int)(i % C_);
    float gate = 1.0f / (1.0f + expf(-heat[row]));
    float tv = t[i];
    out[i] = tv + tv * saw[c] * gate;
}

// ---------------- attm copy ----------------
__global__ void k_attm(const float* __restrict__ asum, float* __restrict__ out) {
    size_t idx = (size_t)blockIdx.x * 256 + threadIdx.x;
    size_t total = (size_t)B_ * 256 * 256;
    if (idx >= total) return;
    size_t b = idx / 65536;
    size_t r = idx % 65536;
    int i = (int)(r >> 8), j = (int)(r & 255);
    out[idx] = asum[(size_t)b * N_ * N_ + (size_t)(i + 1) * N_ + (j + 1)];
}

// ---------------- host orchestration ----------------
static inline dim3 tc_grid(int Nn) { return dim3(Nn / 128, (M_ + 127) / 128); }

extern "C" void kernel_launch(void* const* d_in, const int* in_sizes, int n_in,
                              void* d_out, int out_size) {
    const float* in_src   = (const float*)d_in[0];
    const float* in_tgt   = (const float*)d_in[1];
    const float* sattn_qkv_w  = (const float*)d_in[2];
    const float* sattn_proj_w = (const float*)d_in[3];
    const float* sattn_proj_b = (const float*)d_in[4];
    const float* cattn_qkv_w  = (const float*)d_in[5];
    const float* cattn_proj_w = (const float*)d_in[6];
    const float* cattn_proj_b = (const float*)d_in[7];
    const float* n1g = (const float*)d_in[8];
    const float* n1b = (const float*)d_in[9];
    const float* n2g = (const float*)d_in[10];
    const float* n2b = (const float*)d_in[11];
    const float* fc1_w = (const float*)d_in[12];
    const float* fc1_b = (const float*)d_in[13];
    const float* fc2_w = (const float*)d_in[14];
    const float* fc2_b = (const float*)d_in[15];
    const float* saw   = (const float*)d_in[16];
    const float* pos   = (const float*)d_in[17];

    float *s, *t, *ln, *q1, *q2, *at, *ob, *sc, *hd, *tp, *as_, *ht;
    cudaGetSymbolAddress((void**)&s,   g_s);
    cudaGetSymbolAddress((void**)&t,   g_t);
    cudaGetSymbolAddress((void**)&ln,  g_ln);
    cudaGetSymbolAddress((void**)&q1,  g_q1);
    cudaGetSymbolAddress((void**)&q2,  g_q2);
    cudaGetSymbolAddress((void**)&at,  g_att);
    cudaGetSymbolAddress((void**)&ob,  g_o);
    cudaGetSymbolAddress((void**)&sc,  g_sc);
    cudaGetSymbolAddress((void**)&hd,  g_hid);
    cudaGetSymbolAddress((void**)&tp,  g_tmp);
    cudaGetSymbolAddress((void**)&as_, g_asum);
    cudaGetSymbolAddress((void**)&ht,  g_heat);

    cudaFuncSetAttribute((const void*)gemm_mma<0>,
                         cudaFuncAttributeMaxDynamicSharedMemorySize, GEMM_SMEM);
    cudaFuncSetAttribute((const void*)gemm_mma<1>,
                         cudaFuncAttributeMaxDynamicSharedMemorySize, GEMM_SMEM);

    float* out_src  = (float*)d_out;
    float* out_tgt  = out_src + SZ_BNC;
    float* out_attm = out_tgt + SZ_BNC;

    const int EW = (int)((SZ_BNC + 255) / 256);
    dim3 sc_grid(9, 9, B_ * H_);
    int  av_gx = (N_ * D_ + 255) / 256;
    dim3 av_grid(av_gx, B_ * H_);
    int  sm_rows = B_ * H_ * N_;

    // ---- src = src + pos; t = tgt ----
    k_init<<<EW, 256>>>(in_src, in_tgt, pos, s, t);

    // ---- self attention on src ----
    k_ln<<<M_, 256>>>(s, n1g, n1b, ln);
    gemm_mma<0><<<tc_grid(C3_), 256, GEMM_SMEM>>>(ln, sattn_qkv_w, nullptr, q1, M_, C3_, C_);
    k_scores<<<sc_grid, 256>>>(q1, q1, at);
    k_softmax<<<sm_rows, 128>>>(at);
    k_av<<<av_grid, 256>>>(at, q1, ob);
    gemm_mma<0><<<tc_grid(C_), 256, GEMM_SMEM>>>(ob, sattn_proj_w, sattn_proj_b, sc, M_, C_, C_);
    k_add_inplace<<<EW, 256>>>(s, sc, SZ_BNC);
    k_ln<<<M_, 256>>>(sc, n2g, n2b, ln);
    gemm_mma<1><<<tc_grid(HID_), 256, GEMM_SMEM>>>(ln, fc1_w, fc1_b, hd, M_, HID_, C_);
    gemm_mma<0><<<tc_grid(C_), 256, GEMM_SMEM>>>(hd, fc2_w, fc2_b, tp, M_, C_, HID_);
    k_add_inplace<<<EW, 256>>>(s, tp, SZ_BNC);

    // ---- self attention on tgt ----
    k_ln<<<M_, 256>>>(t, n1g, n1b, ln);
    gemm_mma<0><<<tc_grid(C3_), 256, GEMM_SMEM>>>(ln, sattn_qkv_w, nullptr, q1, M_, C3_, C_);
    k_scores<<<sc_grid, 256>>>(q1, q1, at);
    k_softmax<<<sm_rows, 128>>>(at);
    k_av<<<av_grid, 256>>>(at, q1, ob);
    gemm_mma<0><<<tc_grid(C_), 256, GEMM_SMEM>>>(ob, sattn_proj_w, sattn_proj_b, sc, M_, C_, C_);
    k_add_inplace<<<EW, 256>>>(t, sc, SZ_BNC);
    k_ln<<<M_, 256>>>(sc, n2g, n2b, ln);
    gemm_mma<1><<<tc_grid(HID_), 256, GEMM_SMEM>>>(ln, fc1_w, fc1_b, hd, M_, HID_, C_);
    gemm_mma<0><<<tc_grid(C_), 256, GEMM_SMEM>>>(hd, fc2_w, fc2_b, tp, M_, C_, HID_);
    k_add_inplace<<<EW, 256>>>(t, tp, SZ_BNC);

    // ---- cross attention ----
    k_ln<<<M_, 256>>>(s, n1g, n1b, ln);
    gemm_mma<0><<<tc_grid(C3_), 256, GEMM_SMEM>>>(ln, cattn_qkv_w, nullptr, q1, M_, C3_, C_);
    k_ln<<<M_, 256>>>(t, n1g, n1b, ln);
    gemm_mma<0><<<tc_grid(C3_), 256, GEMM_SMEM>>>(ln, cattn_qkv_w, nullptr, q2, M_, C3_, C_);
    k_scores<<<sc_grid, 256>>>(q1, q2, at);
    k_softmax<<<sm_rows, 128>>>(at);
    k_headsum<<<(int)((SZ_ASUM + 255) / 256), 256>>>(at, as_);
    k_av<<<av_grid, 256>>>(at, q2, ob);
    gemm_mma<0><<<tc_grid(C_), 256, GEMM_SMEM>>>(ob, cattn_proj_w, cattn_proj_b, sc, M_, C_, C_);
    k_arf<<<EW, 256>>>(sc, SZ_BNC);
    k_add_inplace<<<EW, 256>>>(s, sc, SZ_BNC);
    k_ln<<<M_, 256>>>(sc, n2g, n2b, ln);
    gemm_mma<1><<<tc_grid(HID_), 256, GEMM_SMEM>>>(ln, fc1_w, fc1_b, hd, M_, HID_, C_);
    gemm_mma<0><<<tc_grid(C_), 256, GEMM_SMEM>>>(hd, fc2_w, fc2_b, tp, M_, C_, HID_);
    k_add_out<<<EW, 256>>>(s, tp, out_src, SZ_BNC);

    // ---- gate + tgt out ----
    k_heat<<<(B_ * N_ + 255) / 256, 256>>>(as_, ht);
    k_tgt_out<<<EW, 256>>>(t, saw, ht, out_tgt);

    // ---- attm out ----
    k_attm<<<(int)(((size_t)B_ * 256 * 256 + 255) / 256), 256>>>(as_, out_attm);
}

// round 6
// speedup vs baseline: 2.0502x; 1.0968x over previous
#include <cuda_runtime.h>
#include <cuda_bf16.h>
#include <math.h>
#include <stdint.h>

// ---------------- problem constants ----------------
constexpr int B_  = 64;
constexpr int N_  = 257;
constexpr int C_  = 768;
constexpr int H_  = 12;
constexpr int D_  = 64;           // C_/H_
constexpr int HID_ = 3072;
constexpr int M_  = B_ * N_;      // 16448 rows
constexpr int C3_ = 3 * C_;       // 2304

constexpr size_t SZ_BNC  = (size_t)M_ * C_;
constexpr size_t SZ_QKV  = (size_t)M_ * C3_;
constexpr size_t SZ_ATT  = (size_t)B_ * H_ * N_ * N_;
constexpr size_t SZ_HID  = (size_t)M_ * HID_;
constexpr size_t SZ_ASUM = (size_t)B_ * N_ * N_;

// ---------------- device scratch (static, no allocs) ----------------
__device__ float g_s   [SZ_BNC];
__device__ float g_t   [SZ_BNC];
__device__ float g_ln  [SZ_BNC];
__device__ float g_q1  [SZ_QKV];
__device__ float g_q2  [SZ_QKV];
__device__ float g_att [SZ_ATT];
__device__ float g_o   [SZ_BNC];
__device__ float g_sc  [SZ_BNC];
__device__ float g_hid [SZ_HID];
__device__ float g_tmp [SZ_BNC];
__device__ float g_asum[SZ_ASUM];
__device__ float g_heat[(size_t)B_ * N_];

// ================= helpers =================
__device__ __forceinline__ uint32_t smem_u32(const void* p) {
    uint32_t a;
    asm("{ .reg .u64 t; cvta.to.shared.u64 t, %1; cvt.u32.u64 %0, t; }"
        : "=r"(a) : "l"(p));
    return a;
}

#define SW128(o) ((o) ^ (((o) >> 3) & 0x70))

#define LDSM_X4(r0, r1, r2, r3, addr) \
    asm volatile("ldmatrix.sync.aligned.m8n8.x4.shared.b16 {%0,%1,%2,%3}, [%4];" \
        : "=r"(r0), "=r"(r1), "=r"(r2), "=r"(r3) : "r"(addr))

#define LDSM_X2(r0, r1, addr) \
    asm volatile("ldmatrix.sync.aligned.m8n8.x2.shared.b16 {%0,%1}, [%2];" \
        : "=r"(r0), "=r"(r1) : "r"(addr))

#define MMA16816(d, a, b0, b1) \
    asm volatile("mma.sync.aligned.m16n8k16.row.col.f32.bf16.bf16.f32 " \
        "{%0,%1,%2,%3},{%4,%5,%6,%7},{%8,%9},{%0,%1,%2,%3};" \
        : "+f"((d)[0]), "+f"((d)[1]), "+f"((d)[2]), "+f"((d)[3]) \
        : "r"((a)[0]), "r"((a)[1]), "r"((a)[2]), "r"((a)[3]), "r"(b0), "r"(b1))

#define MMA_TF32(d, a, b0, b1) \
    asm volatile("mma.sync.aligned.m16n8k8.row.col.f32.tf32.tf32.f32 " \
        "{%0,%1,%2,%3},{%4,%5,%6,%7},{%8,%9},{%0,%1,%2,%3};" \
        : "+f"((d)[0]), "+f"((d)[1]), "+f"((d)[2]), "+f"((d)[3]) \
        : "r"((a)[0]), "r"((a)[1]), "r"((a)[2]), "r"((a)[3]), "r"(b0), "r"(b1))

__device__ __forceinline__ uint32_t f2tf(float f) {
    uint32_t r;
    asm("cvt.rna.tf32.f32 %0, %1;" : "=r"(r) : "f"(f));
    return r;
}

// split one fp32 x8 into hi/lo bf16x2 quads
__device__ __forceinline__ void cvt_hilo8(const float* x, uint4& hq, uint4& lq) {
    uint32_t hp[4], lp[4];
#pragma unroll
    for (int i = 0; i < 4; i++) {
        float a = x[2 * i], b = x[2 * i + 1];
        __nv_bfloat162 h2 = __float22bfloat162_rn(make_float2(a, b));
        uint32_t h = *(uint32_t*)&h2;
        hp[i] = h;
        float fa = __uint_as_float(h << 16);
        float fb = __uint_as_float(h & 0xFFFF0000u);
        __nv_bfloat162 l2 = __float22bfloat162_rn(make_float2(a - fa, b - fb));
        lp[i] = *(uint32_t*)&l2;
    }
    hq = make_uint4(hp[0], hp[1], hp[2], hp[3]);
    lq = make_uint4(lp[0], lp[1], lp[2], lp[3]);
}

// ================= split-bf16 mma.sync GEMM =================
constexpr uint32_t T_AH = 0;
constexpr uint32_t T_AL = 8192;
constexpr uint32_t T_BH = 16384;
constexpr uint32_t T_BL = 24576;
constexpr uint32_t STAGE = 32768;
constexpr int GEMM_SMEM = 65536;

template<int ACT>
__global__ __launch_bounds__(256, 1)
void gemm_mma(const float* __restrict__ A, const float* __restrict__ W,
              const float* __restrict__ bias, float* __restrict__ Cmat,
              int M, int Nn, int K) {
    extern __shared__ __align__(1024) char smem[];
    const uint32_t sb = smem_u32(smem);
    const int tid  = threadIdx.x;
    const int wid  = tid >> 5;
    const int lane = tid & 31;
    const int bm   = blockIdx.y * 128;
    const int bn   = blockIdx.x * 128;
    const int wm   = (wid & 3) * 32;
    const int wn   = (wid >> 2) * 64;

    const int lr = tid >> 1;
    const int lk = (tid & 1) * 16;
    const bool aOk = (bm + lr) < M;
    const float* Ap = A + (size_t)(bm + lr) * K + lk;
    const float* Wp = W + (size_t)(bn + lr) * K + lk;

    float acc[2][8][4];
#pragma unroll
    for (int i = 0; i < 2; i++)
#pragma unroll
        for (int j = 0; j < 8; j++)
#pragma unroll
            for (int r = 0; r < 4; r++) acc[i][j][r] = 0.f;

    float ra[16], rb[16];

#pragma unroll
    for (int u = 0; u < 2; ++u) {
        if (aOk) {
            float4 v0 = *(const float4*)(Ap + u * 8);
            float4 v1 = *(const float4*)(Ap + u * 8 + 4);
            ra[u*8+0]=v0.x; ra[u*8+1]=v0.y; ra[u*8+2]=v0.z; ra[u*8+3]=v0.w;
            ra[u*8+4]=v1.x; ra[u*8+5]=v1.y; ra[u*8+6]=v1.z; ra[u*8+7]=v1.w;
        } else {
#pragma unroll
            for (int q = 0; q < 8; q++) ra[u*8+q] = 0.f;
        }
        float4 w0 = *(const float4*)(Wp + u * 8);
        float4 w1 = *(const float4*)(Wp + u * 8 + 4);
        rb[u*8+0]=w0.x; rb[u*8+1]=w0.y; rb[u*8+2]=w0.z; rb[u*8+3]=w0.w;
        rb[u*8+4]=w1.x; rb[u*8+5]=w1.y; rb[u*8+6]=w1.z; rb[u*8+7]=w1.w;
    }
    {
        const uint32_t soff = lr * 64u;
#pragma unroll
        for (int u = 0; u < 2; ++u) {
            uint32_t off = soff + (uint32_t)(lk + u * 8) * 2u;
            uint32_t sw = SW128(off);
            uint4 hq, lq;
            cvt_hilo8(&ra[u * 8], hq, lq);
            *(uint4*)(smem + T_AH + sw) = hq;
            *(uint4*)(smem + T_AL + sw) = lq;
            cvt_hilo8(&rb[u * 8], hq, lq);
            *(uint4*)(smem + T_BH + sw) = hq;
            *(uint4*)(smem + T_BL + sw) = lq;
        }
    }
    __syncthreads();

    const int nit = K >> 5;
    for (int it = 0; it < nit; ++it) {
        if (it + 1 < nit) {
            const int k0 = (it + 1) << 5;
#pragma unroll
            for (int u = 0; u < 2; ++u) {
                if (aOk) {
                    float4 v0 = *(const float4*)(Ap + k0 + u * 8);
                    float4 v1 = *(const float4*)(Ap + k0 + u * 8 + 4);
                    ra[u*8+0]=v0.x; ra[u*8+1]=v0.y; ra[u*8+2]=v0.z; ra[u*8+3]=v0.w;
                    ra[u*8+4]=v1.x; ra[u*8+5]=v1.y; ra[u*8+6]=v1.z; ra[u*8+7]=v1.w;
                } else {
#pragma unroll
                    for (int q = 0; q < 8; q++) ra[u*8+q] = 0.f;
                }
                float4 w0 = *(const float4*)(Wp + k0 + u * 8);
                float4 w1 = *(const float4*)(Wp + k0 + u * 8 + 4);
                rb[u*8+0]=w0.x; rb[u*8+1]=w0.y; rb[u*8+2]=w0.z; rb[u*8+3]=w0.w;
                rb[u*8+4]=w1.x; rb[u*8+5]=w1.y; rb[u*8+6]=w1.z; rb[u*8+7]=w1.w;
            }
        }

        const uint32_t stb = sb + (uint32_t)(it & 1) * STAGE;
#pragma unroll
        for (int ks = 0; ks < 2; ++ks) {
            const int kk = ks * 16;
            uint32_t ah[2][4], al[2][4];
#pragma unroll
            for (int mt = 0; mt < 2; ++mt) {
                uint32_t off = (uint32_t)(wm + mt * 16 + (lane & 15)) * 64u
                             + (uint32_t)(kk + (lane >> 4) * 8) * 2u;
                uint32_t sw = SW128(off);
                LDSM_X4(ah[mt][0], ah[mt][1], ah[mt][2], ah[mt][3], stb + T_AH + sw);
                LDSM_X4(al[mt][0], al[mt][1], al[mt][2], al[mt][3], stb + T_AL + sw);
            }
#pragma unroll
            for (int nt = 0; nt < 8; ++nt) {
                const int l8 = lane & 15;
                uint32_t boff = (uint32_t)(wn + nt * 8 + (l8 & 7)) * 64u
                              + (uint32_t)(kk + ((l8 >> 3) & 1) * 8) * 2u;
                uint32_t bsw = SW128(boff);
                uint32_t b0, b1, c0, c1;
                LDSM_X2(b0, b1, stb + T_BH + bsw);
                LDSM_X2(c0, c1, stb + T_BL + bsw);
#pragma unroll
                for (int mt = 0; mt < 2; ++mt) {
                    MMA16816(acc[mt][nt], ah[mt], b0, b1);
                    MMA16816(acc[mt][nt], ah[mt], c0, c1);
                    MMA16816(acc[mt][nt], al[mt], b0, b1);
                }
            }
        }

        if (it + 1 < nit) {
            const uint32_t base = (uint32_t)((it + 1) & 1) * STAGE;
            const uint32_t soff = lr * 64u;
#pragma unroll
            for (int u = 0; u < 2; ++u) {
                uint32_t off = soff + (uint32_t)(lk + u * 8) * 2u;
                uint32_t sw = SW128(off);
                uint4 hq, lq;
                cvt_hilo8(&ra[u * 8], hq, lq);
                *(uint4*)(smem + base + T_AH + sw) = hq;
                *(uint4*)(smem + base + T_AL + sw) = lq;
                cvt_hilo8(&rb[u * 8], hq, lq);
                *(uint4*)(smem + base + T_BH + sw) = hq;
                *(uint4*)(smem + base + T_BL + sw) = lq;
            }
        }
        __syncthreads();
    }

#pragma unroll
    for (int mt = 0; mt < 2; ++mt) {
#pragma unroll
        for (int half = 0; half < 2; ++half) {
            const int row = bm + wm + mt * 16 + (lane >> 2) + half * 8;
            if (row < M) {
#pragma unroll
                for (int nt = 0; nt < 8; ++nt) {
                    const int col = bn + wn + nt * 8 + (lane & 3) * 2;
                    float v0 = acc[mt][nt][half * 2 + 0];
                    float v1 = acc[mt][nt][half * 2 + 1];
                    if (bias) { v0 += bias[col]; v1 += bias[col + 1]; }
                    if (ACT == 1) {
                        v0 = 0.5f * v0 * (1.0f + erff(v0 * 0.70710678118654752f));
                        v1 = 0.5f * v1 * (1.0f + erff(v1 * 0.70710678118654752f));
                    }
                    *(float2*)&Cmat[(size_t)row * Nn + col] = make_float2(v0, v1);
                }
            }
        }
    }
}

// ================= fused flash attention (tf32 mma) =================
// One CTA = one (b,h) x 64 q-rows. K/V fully resident in smem.
// Phase1: S = 0.125 * Q K^T (tf32 mma). Phase2: softmax rows in smem.
// Phase3: O = P V with 2-term split on P. Optionally stream P to global.
constexpr int FA_NK  = 264;   // keys padded to 33*8
constexpr int FA_KST = 68;    // K smem stride (68 % 32 == 4 -> conflict-free frags)
constexpr int FA_SST = 268;   // S / Vt stride (268 % 32 == 12 -> conflict-free)
constexpr int FA_OFF_Q = 0;                       // 64 x 68
constexpr int FA_OFF_K = 64 * FA_KST;             // 264 x 68 (Vt 64 x 268 overlays)
constexpr int FA_OFF_S = FA_OFF_K + FA_NK * FA_KST;  // 64 x 268
constexpr int FA_FLOATS = FA_OFF_S + 64 * FA_SST;
constexpr int FATT_SMEM = FA_FLOATS * 4;          // 157,824 B

template<int WRITE_P>
__global__ __launch_bounds__(128, 1)
void k_fattn(const float* __restrict__ qsrc, const float* __restrict__ kvsrc,
             float* __restrict__ o, float* __restrict__ pout) {
    extern __shared__ __align__(16) float fs[];
    float* Qs = fs + FA_OFF_Q;
    float* Ks = fs + FA_OFF_K;   // also Vt in phase 3
    float* Ss = fs + FA_OFF_S;

    const int q0 = blockIdx.x * 64;
    const int bh = blockIdx.y;
    const int b = bh / H_, h = bh % H_;
    const int tid = threadIdx.x;
    const int wid = tid >> 5;
    const int lane = tid & 31;
    const int gid = lane >> 2;     // 0..7
    const int tig = lane & 3;      // 0..3
    const int r0 = wid * 16;

    const float* Qg = qsrc + (size_t)b * N_ * C3_ + h * D_;
    const float* Kg = kvsrc + (size_t)b * N_ * C3_ + C_ + h * D_;
    const float* Vg = kvsrc + (size_t)b * N_ * C3_ + 2 * C_ + h * D_;

    // ---- load Q block (64 x 64) ----
    for (int idx = tid; idx < 64 * 64; idx += 128) {
        int r = idx >> 6, d = idx & 63;
        int q = q0 + r;
        Qs[r * FA_KST + d] = (q < N_) ? Qg[(size_t)q * C3_ + d] : 0.f;
    }
    // ---- load K (264 x 64) ----
    for (int idx = tid; idx < FA_NK * 64; idx += 128) {
        int r = idx >> 6, d = idx & 63;
        Ks[r * FA_KST + d] = (r < N_) ? Kg[(size_t)r * C3_ + d] : 0.f;
    }
    __syncthreads();

    // ---- phase 1: scores ----
    {
        uint32_t a[8][4];
#pragma unroll
        for (int ks = 0; ks < 8; ++ks) {
            a[ks][0] = f2tf(Qs[(r0 + gid)     * FA_KST + ks * 8 + tig]);
            a[ks][1] = f2tf(Qs[(r0 + gid + 8) * FA_KST + ks * 8 + tig]);
            a[ks][2] = f2tf(Qs[(r0 + gid)     * FA_KST + ks * 8 + 4 + tig]);
            a[ks][3] = f2tf(Qs[(r0 + gid + 8) * FA_KST + ks * 8 + 4 + tig]);
        }
#pragma unroll 1
        for (int nt = 0; nt < 33; ++nt) {
            float c[4] = {0.f, 0.f, 0.f, 0.f};
#pragma unroll
            for (int ks = 0; ks < 8; ++ks) {
                uint32_t b0 = f2tf(Ks[(nt * 8 + gid) * FA_KST + ks * 8 + tig]);
                uint32_t b1 = f2tf(Ks[(nt * 8 + gid) * FA_KST + ks * 8 + 4 + tig]);
                MMA_TF32(c, a[ks], b0, b1);
            }
            Ss[(r0 + gid)     * FA_SST + nt * 8 + tig * 2]     = c[0] * 0.125f;
            Ss[(r0 + gid)     * FA_SST + nt * 8 + tig * 2 + 1] = c[1] * 0.125f;
            Ss[(r0 + gid + 8) * FA_SST + nt * 8 + tig * 2]     = c[2] * 0.125f;
            Ss[(r0 + gid + 8) * FA_SST + nt * 8 + tig * 2 + 1] = c[3] * 0.125f;
        }
    }
    __syncwarp();

    // ---- phase 2: softmax on own 16 rows ----
#pragma unroll 1
    for (int rr = 0; rr < 16; ++rr) {
        const int row = r0 + rr;
        const int q = q0 + row;
        if (q >= N_) continue;
        float* Sr = Ss + (size_t)row * FA_SST;
        float m = -1e30f;
        for (int c = lane; c < N_; c += 32) m = fmaxf(m, Sr[c]);
#pragma unroll
        for (int off = 16; off > 0; off >>= 1)
            m = fmaxf(m, __shfl_xor_sync(0xFFFFFFFF, m, off));
        float sum = 0.f;
        for (int c = lane; c < N_; c += 32) {
            float e = expf(Sr[c] - m);
            Sr[c] = e;
            sum += e;
        }
#pragma unroll
        for (int off = 16; off > 0; off >>= 1)
            sum += __shfl_xor_sync(0xFFFFFFFF, sum, off);
        const float inv = 1.0f / sum;
        for (int c = lane; c < FA_NK; c += 32) {
            float p = (c < N_) ? Sr[c] * inv : 0.f;
            Sr[c] = p;
            if (WRITE_P && c < N_)
                pout[(size_t)bh * N_ * N_ + (size_t)q * N_ + c] = p;
        }
    }
    __syncthreads();

    // ---- phase 3: load V transposed into K's smem, then O = P V ----
    float* Vt = Ks;
    for (int idx = tid; idx < FA_NK * 64; idx += 128) {
        int key = idx >> 6, d = idx & 63;
        float v = (key < N_) ? Vg[(size_t)key * C3_ + d] : 0.f;
        Vt[d * FA_SST + key] = v;
    }
    __syncthreads();

    float oa[8][4];
#pragma unroll
    for (int nt = 0; nt < 8; ++nt)
#pragma unroll
        for (int r = 0; r < 4; ++r) oa[nt][r] = 0.f;

#pragma unroll 1
    for (int ks = 0; ks < 33; ++ks) {
        float p0 = Ss[(r0 + gid)     * FA_SST + ks * 8 + tig];
        float p1 = Ss[(r0 + gid + 8) * FA_SST + ks * 8 + tig];
        float p2 = Ss[(r0 + gid)     * FA_SST + ks * 8 + 4 + tig];
        float p3 = Ss[(r0 + gid + 8) * FA_SST + ks * 8 + 4 + tig];
        uint32_t ah[4], al[4];
        ah[0] = f2tf(p0); al[0] = __float_as_uint(p0 - __uint_as_float(ah[0]));
        ah[1] = f2tf(p1); al[1] = __float_as_uint(p1 - __uint_as_float(ah[1]));
        ah[2] = f2tf(p2); al[2] = __float_as_uint(p2 - __uint_as_float(ah[2]));
        ah[3] = f2tf(p3); al[3] = __float_as_uint(p3 - __uint_as_float(ah[3]));
#pragma unroll
        for (int nt = 0; nt < 8; ++nt) {
            uint32_t b0 = f2tf(Vt[(nt * 8 + gid) * FA_SST + ks * 8 + tig]);
            uint32_t b1 = f2tf(Vt[(nt * 8 + gid) * FA_SST + ks * 8 + 4 + tig]);
            MMA_TF32(oa[nt], ah, b0, b1);
            MMA_TF32(oa[nt], al, b0, b1);
        }
    }

    // ---- write O ----
    {
        const int q_a = q0 + r0 + gid;
        const int q_b = q_a + 8;
#pragma unroll
        for (int nt = 0; nt < 8; ++nt) {
            const int col = h * D_ + nt * 8 + tig * 2;
            if (q_a < N_)
                *(float2*)&o[((size_t)(b * N_ + q_a)) * C_ + col] =
                    make_float2(oa[nt][0], oa[nt][1]);
            if (q_b < N_)
                *(float2*)&o[((size_t)(b * N_ + q_b)) * C_ + col] =
                    make_float2(oa[nt][2], oa[nt][3]);
        }
    }
}

// ---------------- elementwise kernels ----------------
__global__ void k_init(const float* __restrict__ src, const float* __restrict__ tgt,
                       const float* __restrict__ pos, float* __restrict__ s,
                       float* __restrict__ t) {
    size_t i = (size_t)blockIdx.x * blockDim.x + threadIdx.x;
    if (i >= SZ_BNC) return;
    size_t nc = i % ((size_t)N_ * C_);
    s[i] = src[i] + pos[nc];
    t[i] = tgt[i];
}

__global__ void k_add_inplace(float* __restrict__ y, const float* __restrict__ x, size_t n) {
    size_t i = (size_t)blockIdx.x * blockDim.x + threadIdx.x;
    if (i < n) y[i] += x[i];
}

__global__ void k_add_out(const float* __restrict__ a, const float* __restrict__ b,
                          float* __restrict__ out, size_t n) {
    size_t i = (size_t)blockIdx.x * blockDim.x + threadIdx.x;
    if (i < n) out[i] = a[i] + b[i];
}

__global__ void k_arf(float* __restrict__ x, size_t n) {
    size_t i = (size_t)blockIdx.x * blockDim.x + threadIdx.x;
    if (i >= n) return;
    float v = x[i];
    float ep = expf(v), en = expf(-v), en4 = expf(-v - 4.0f);
    float tmp = (ep - en) / (ep + en4);
    x[i] = tmp < 0.0f ? 0.0f : tmp;
}

// ---------------- layernorm ----------------
__global__ void k_ln(const float* __restrict__ x, const float* __restrict__ g,
                     const float* __restrict__ b, float* __restrict__ y) {
    int row = blockIdx.x;
    int tid = threadIdx.x;
    const float* xr = x + (size_t)row * C_;
    float s = 0.f, q = 0.f;
    for (int i = tid; i < C_; i += 256) { float v = xr[i]; s += v; q += v * v; }
    __shared__ float rs[256], rq[256];
    rs[tid] = s; rq[tid] = q; __syncthreads();
    for (int o = 128; o > 0; o >>= 1) {
        if (tid < o) { rs[tid] += rs[tid + o]; rq[tid] += rq[tid + o]; }
        __syncthreads();
    }
    float mean = rs[0] * (1.0f / C_);
    float var  = rq[0] * (1.0f / C_) - mean * mean;
    float inv  = rsqrtf(var + 1e-5f);
    float* yr = y + (size_t)row * C_;
    for (int i = tid; i < C_; i += 256)
        yr[i] = (xr[i] - mean) * inv * g[i] + b[i];
}

// ---------------- head sum ----------------
__global__ void k_headsum(const float* __restrict__ attn, float* __restrict__ asum) {
    size_t idx = (size_t)blockIdx.x * 256 + threadIdx.x;
    if (idx >= SZ_ASUM) return;
    size_t b = idx / ((size_t)N_ * N_);
    size_t r = idx % ((size_t)N_ * N_);
    float s = 0.f;
    for (int h = 0; h < H_; h++) s += attn[((size_t)(b * H_ + h)) * N_ * N_ + r];
    asum[idx] = s;
}

// ---------------- heat ----------------
__global__ void k_heat(const float* __restrict__ asum, float* __restrict__ heat) {
    int idx = blockIdx.x * 256 + threadIdx.x;
    if (idx >= B_ * N_) return;
    int b = idx / N_, m = idx % N_;
    const float* p = asum + (size_t)b * N_ * N_ + m;
    float s = 0.f;
    for (int n = 0; n < N_; n++) s += p[(size_t)n * N_];
    heat[idx] = s * (1.0f / N_);
}

// ---------------- tgt output ----------------
__global__ void k_tgt_out(const float* __restrict__ t, const float* __restrict__ saw,
                          const float* __restrict__ heat, float* __restrict__ out) {
    size_t i = (size_t)blockIdx.x * 256 + threadIdx.x;
    if (i >= SZ_BNC) return;
    int row = (int)(i / C_);
    int c   = (int)(i % C_);
    float gate = 1.0f / (1.0f + expf(-heat[row]));
    float tv = t[i];
    out[i] = tv + tv * saw[c] * gate;
}

// ---------------- attm copy ----------------
__global__ void k_attm(const float* __restrict__ asum, float* __restrict__ out) {
    size_t idx = (size_t)blockIdx.x * 256 + threadIdx.x;
    size_t total = (size_t)B_ * 256 * 256;
    if (idx >= total) return;
    size_t b = idx / 65536;
    size_t r = idx % 65536;
    int i = (int)(r >> 8), j = (int)(r & 255);
    out[idx] = asum[(size_t)b * N_ * N_ + (size_t)(i + 1) * N_ + (j + 1)];
}

// ---------------- host orchestration ----------------
static inline dim3 tc_grid(int Nn) { return dim3(Nn / 128, (M_ + 127) / 128); }

extern "C" void kernel_launch(void* const* d_in, const int* in_sizes, int n_in,
                              void* d_out, int out_size) {
    const float* in_src   = (const float*)d_in[0];
    const float* in_tgt   = (const float*)d_in[1];
    const float* sattn_qkv_w  = (const float*)d_in[2];
    const float* sattn_proj_w = (const float*)d_in[3];
    const float* sattn_proj_b = (const float*)d_in[4];
    const float* cattn_qkv_w  = (const float*)d_in[5];
    const float* cattn_proj_w = (const float*)d_in[6];
    const float* cattn_proj_b = (const float*)d_in[7];
    const float* n1g = (const float*)d_in[8];
    const float* n1b = (const float*)d_in[9];
    const float* n2g = (const float*)d_in[10];
    const float* n2b = (const float*)d_in[11];
    const float* fc1_w = (const float*)d_in[12];
    const float* fc1_b = (const float*)d_in[13];
    const float* fc2_w = (const float*)d_in[14];
    const float* fc2_b = (const float*)d_in[15];
    const float* saw   = (const float*)d_in[16];
    const float* pos   = (const float*)d_in[17];

    float *s, *t, *ln, *q1, *q2, *at, *ob, *sc, *hd, *tp, *as_, *ht;
    cudaGetSymbolAddress((void**)&s,   g_s);
    cudaGetSymbolAddress((void**)&t,   g_t);
    cudaGetSymbolAddress((void**)&ln,  g_ln);
    cudaGetSymbolAddress((void**)&q1,  g_q1);
    cudaGetSymbolAddress((void**)&q2,  g_q2);
    cudaGetSymbolAddress((void**)&at,  g_att);
    cudaGetSymbolAddress((void**)&ob,  g_o);
    cudaGetSymbolAddress((void**)&sc,  g_sc);
    cudaGetSymbolAddress((void**)&hd,  g_hid);
    cudaGetSymbolAddress((void**)&tp,  g_tmp);
    cudaGetSymbolAddress((void**)&as_, g_asum);
    cudaGetSymbolAddress((void**)&ht,  g_heat);

    cudaFuncSetAttribute((const void*)gemm_mma<0>,
                         cudaFuncAttributeMaxDynamicSharedMemorySize, GEMM_SMEM);
    cudaFuncSetAttribute((const void*)gemm_mma<1>,
                         cudaFuncAttributeMaxDynamicSharedMemorySize, GEMM_SMEM);
    cudaFuncSetAttribute((const void*)k_fattn<0>,
                         cudaFuncAttributeMaxDynamicSharedMemorySize, FATT_SMEM);
    cudaFuncSetAttribute((const void*)k_fattn<1>,
                         cudaFuncAttributeMaxDynamicSharedMemorySize, FATT_SMEM);

    float* out_src  = (float*)d_out;
    float* out_tgt  = out_src + SZ_BNC;
    float* out_attm = out_tgt + SZ_BNC;

    const int EW = (int)((SZ_BNC + 255) / 256);
    dim3 fa_grid((N_ + 63) / 64, B_ * H_);

    // ---- src = src + pos; t = tgt ----
    k_init<<<EW, 256>>>(in_src, in_tgt, pos, s, t);

    // ---- self attention on src ----
    k_ln<<<M_, 256>>>(s, n1g, n1b, ln);
    gemm_mma<0><<<tc_grid(C3_), 256, GEMM_SMEM>>>(ln, sattn_qkv_w, nullptr, q1, M_, C3_, C_);
    k_fattn<0><<<fa_grid, 128, FATT_SMEM>>>(q1, q1, ob, nullptr);
    gemm_mma<0><<<tc_grid(C_), 256, GEMM_SMEM>>>(ob, sattn_proj_w, sattn_proj_b, sc, M_, C_, C_);
    k_add_inplace<<<EW, 256>>>(s, sc, SZ_BNC);
    k_ln<<<M_, 256>>>(sc, n2g, n2b, ln);
    gemm_mma<1><<<tc_grid(HID_), 256, GEMM_SMEM>>>(ln, fc1_w, fc1_b, hd, M_, HID_, C_);
    gemm_mma<0><<<tc_grid(C_), 256, GEMM_SMEM>>>(hd, fc2_w, fc2_b, tp, M_, C_, HID_);
    k_add_inplace<<<EW, 256>>>(s, tp, SZ_BNC);

    // ---- self attention on tgt ----
    k_ln<<<M_, 256>>>(t, n1g, n1b, ln);
    gemm_mma<0><<<tc_grid(C3_), 256, GEMM_SMEM>>>(ln, sattn_qkv_w, nullptr, q1, M_, C3_, C_);
    k_fattn<0><<<fa_grid, 128, FATT_SMEM>>>(q1, q1, ob, nullptr);
    gemm_mma<0><<<tc_grid(C_), 256, GEMM_SMEM>>>(ob, sattn_proj_w, sattn_proj_b, sc, M_, C_, C_);
    k_add_inplace<<<EW, 256>>>(t, sc, SZ_BNC);
    k_ln<<<M_, 256>>>(sc, n2g, n2b, ln);
    gemm_mma<1><<<tc_grid(HID_), 256, GEMM_SMEM>>>(ln, fc1_w, fc1_b, hd, M_, HID_, C_);
    gemm_mma<0><<<tc_grid(C_), 256, GEMM_SMEM>>>(hd, fc2_w, fc2_b, tp, M_, C_, HID_);
    k_add_inplace<<<EW, 256>>>(t, tp, SZ_BNC);

    // ---- cross attention ----
    k_ln<<<M_, 256>>>(s, n1g, n1b, ln);
    gemm_mma<0><<<tc_grid(C3_), 256, GEMM_SMEM>>>(ln, cattn_qkv_w, nullptr, q1, M_, C3_, C_);
    k_ln<<<M_, 256>>>(t, n1g, n1b, ln);
    gemm_mma<0><<<tc_grid(C3_), 256, GEMM_SMEM>>>(ln, cattn_qkv_w, nullptr, q2, M_, C3_, C_);
    k_fattn<1><<<fa_grid, 128, FATT_SMEM>>>(q1, q2, ob, at);
    k_headsum<<<(int)((SZ_ASUM + 255) / 256), 256>>>(at, as_);
    gemm_mma<0><<<tc_grid(C_), 256, GEMM_SMEM>>>(ob, cattn_proj_w, cattn_proj_b, sc, M_, C_, C_);
    k_arf<<<EW, 256>>>(sc, SZ_BNC);
    k_add_inplace<<<EW, 256>>>(s, sc, SZ_BNC);
    k_ln<<<M_, 256>>>(sc, n2g, n2b, ln);
    gemm_mma<1><<<tc_grid(HID_), 256, GEMM_SMEM>>>(ln, fc1_w, fc1_b, hd, M_, HID_, C_);
    gemm_mma<0><<<tc_grid(C_), 256, GEMM_SMEM>>>(hd, fc2_w, fc2_b, tp, M_, C_, HID_);
    k_add_out<<<EW, 256>>>(s, tp, out_src, SZ_BNC);

    // ---- gate + tgt out ----
    k_heat<<<(B_ * N_ + 255) / 256, 256>>>(as_, ht);
    k_tgt_out<<<EW, 256>>>(t, saw, ht, out_tgt);

    // ---- attm out ----
    k_attm<<<(int)(((size_t)B_ * 256 * 256 + 255) / 256), 256>>>(as_, out_attm);
}

// round 7
// speedup vs baseline: 2.4187x; 1.1798x over previous
#include <cuda_runtime.h>
#include <cuda_bf16.h>
#include <math.h>
#include <stdint.h>

// ---------------- problem constants ----------------
constexpr int B_  = 64;
constexpr int N_  = 257;
constexpr int C_  = 768;
constexpr int H_  = 12;
constexpr int D_  = 64;           // C_/H_
constexpr int HID_ = 3072;
constexpr int M_  = B_ * N_;      // 16448 rows
constexpr int C3_ = 3 * C_;       // 2304

constexpr size_t SZ_BNC  = (size_t)M_ * C_;
constexpr size_t SZ_QKV  = (size_t)M_ * C3_;
constexpr size_t SZ_ATT  = (size_t)B_ * H_ * N_ * N_;
constexpr size_t SZ_HID  = (size_t)M_ * HID_;
constexpr size_t SZ_ASUM = (size_t)B_ * N_ * N_;

// ---------------- device scratch (static, no allocs) ----------------
__device__ float g_s   [SZ_BNC];
__device__ float g_t   [SZ_BNC];
__device__ float g_ln  [SZ_BNC];
__device__ float g_q1  [SZ_QKV];
__device__ float g_q2  [SZ_QKV];
__device__ float g_att [SZ_ATT];
__device__ float g_o   [SZ_BNC];
__device__ float g_sc  [SZ_BNC];
__device__ float g_hid [SZ_HID];
__device__ float g_tmp [SZ_BNC];
__device__ float g_asum[SZ_ASUM];
__device__ float g_heat[(size_t)B_ * N_];

// ================= helpers =================
__device__ __forceinline__ uint32_t smem_u32(const void* p) {
    uint32_t a;
    asm("{ .reg .u64 t; cvta.to.shared.u64 t, %1; cvt.u32.u64 %0, t; }"
        : "=r"(a) : "l"(p));
    return a;
}

#define SW128(o) ((o) ^ (((o) >> 3) & 0x70))

#define LDSM_X4(r0, r1, r2, r3, addr) \
    asm volatile("ldmatrix.sync.aligned.m8n8.x4.shared.b16 {%0,%1,%2,%3}, [%4];" \
        : "=r"(r0), "=r"(r1), "=r"(r2), "=r"(r3) : "r"(addr))

#define LDSM_X2(r0, r1, addr) \
    asm volatile("ldmatrix.sync.aligned.m8n8.x2.shared.b16 {%0,%1}, [%2];" \
        : "=r"(r0), "=r"(r1) : "r"(addr))

#define MMA16816(d, a, b0, b1) \
    asm volatile("mma.sync.aligned.m16n8k16.row.col.f32.bf16.bf16.f32 " \
        "{%0,%1,%2,%3},{%4,%5,%6,%7},{%8,%9},{%0,%1,%2,%3};" \
        : "+f"((d)[0]), "+f"((d)[1]), "+f"((d)[2]), "+f"((d)[3]) \
        : "r"((a)[0]), "r"((a)[1]), "r"((a)[2]), "r"((a)[3]), "r"(b0), "r"(b1))

#define MMA_TF32(d, a, b0, b1) \
    asm volatile("mma.sync.aligned.m16n8k8.row.col.f32.tf32.tf32.f32 " \
        "{%0,%1,%2,%3},{%4,%5,%6,%7},{%8,%9},{%0,%1,%2,%3};" \
        : "+f"((d)[0]), "+f"((d)[1]), "+f"((d)[2]), "+f"((d)[3]) \
        : "r"((a)[0]), "r"((a)[1]), "r"((a)[2]), "r"((a)[3]), "r"(b0), "r"(b1))

__device__ __forceinline__ uint32_t f2tf(float f) {
    uint32_t r;
    asm("cvt.rna.tf32.f32 %0, %1;" : "=r"(r) : "f"(f));
    return r;
}

// split one fp32 x8 into hi/lo bf16x2 quads
__device__ __forceinline__ void cvt_hilo8(const float* x, uint4& hq, uint4& lq) {
    uint32_t hp[4], lp[4];
#pragma unroll
    for (int i = 0; i < 4; i++) {
        float a = x[2 * i], b = x[2 * i + 1];
        __nv_bfloat162 h2 = __float22bfloat162_rn(make_float2(a, b));
        uint32_t h = *(uint32_t*)&h2;
        hp[i] = h;
        float fa = __uint_as_float(h << 16);
        float fb = __uint_as_float(h & 0xFFFF0000u);
        __nv_bfloat162 l2 = __float22bfloat162_rn(make_float2(a - fa, b - fb));
        lp[i] = *(uint32_t*)&l2;
    }
    hq = make_uint4(hp[0], hp[1], hp[2], hp[3]);
    lq = make_uint4(lp[0], lp[1], lp[2], lp[3]);
}

// ================= split-bf16 mma.sync GEMM =================
constexpr uint32_t T_AH = 0;
constexpr uint32_t T_AL = 8192;
constexpr uint32_t T_BH = 16384;
constexpr uint32_t T_BL = 24576;
constexpr uint32_t STAGE = 32768;
constexpr int GEMM_SMEM = 65536;

template<int ACT>
__global__ __launch_bounds__(256, 1)
void gemm_mma(const float* __restrict__ A, const float* __restrict__ W,
              const float* __restrict__ bias, float* __restrict__ Cmat,
              int M, int Nn, int K) {
    extern __shared__ __align__(1024) char smem[];
    const uint32_t sb = smem_u32(smem);
    const int tid  = threadIdx.x;
    const int wid  = tid >> 5;
    const int lane = tid & 31;
    const int bm   = blockIdx.y * 128;
    const int bn   = blockIdx.x * 128;
    const int wm   = (wid & 3) * 32;
    const int wn   = (wid >> 2) * 64;

    const int lr = tid >> 1;
    const int lk = (tid & 1) * 16;
    const bool aOk = (bm + lr) < M;
    const float* Ap = A + (size_t)(bm + lr) * K + lk;
    const float* Wp = W + (size_t)(bn + lr) * K + lk;

    float acc[2][8][4];
#pragma unroll
    for (int i = 0; i < 2; i++)
#pragma unroll
        for (int j = 0; j < 8; j++)
#pragma unroll
            for (int r = 0; r < 4; r++) acc[i][j][r] = 0.f;

    float ra[16], rb[16];

#pragma unroll
    for (int u = 0; u < 2; ++u) {
        if (aOk) {
            float4 v0 = *(const float4*)(Ap + u * 8);
            float4 v1 = *(const float4*)(Ap + u * 8 + 4);
            ra[u*8+0]=v0.x; ra[u*8+1]=v0.y; ra[u*8+2]=v0.z; ra[u*8+3]=v0.w;
            ra[u*8+4]=v1.x; ra[u*8+5]=v1.y; ra[u*8+6]=v1.z; ra[u*8+7]=v1.w;
        } else {
#pragma unroll
            for (int q = 0; q < 8; q++) ra[u*8+q] = 0.f;
        }
        float4 w0 = *(const float4*)(Wp + u * 8);
        float4 w1 = *(const float4*)(Wp + u * 8 + 4);
        rb[u*8+0]=w0.x; rb[u*8+1]=w0.y; rb[u*8+2]=w0.z; rb[u*8+3]=w0.w;
        rb[u*8+4]=w1.x; rb[u*8+5]=w1.y; rb[u*8+6]=w1.z; rb[u*8+7]=w1.w;
    }
    {
        const uint32_t soff = lr * 64u;
#pragma unroll
        for (int u = 0; u < 2; ++u) {
            uint32_t off = soff + (uint32_t)(lk + u * 8) * 2u;
            uint32_t sw = SW128(off);
            uint4 hq, lq;
            cvt_hilo8(&ra[u * 8], hq, lq);
            *(uint4*)(smem + T_AH + sw) = hq;
            *(uint4*)(smem + T_AL + sw) = lq;
            cvt_hilo8(&rb[u * 8], hq, lq);
            *(uint4*)(smem + T_BH + sw) = hq;
            *(uint4*)(smem + T_BL + sw) = lq;
        }
    }
    __syncthreads();

    const int nit = K >> 5;
    for (int it = 0; it < nit; ++it) {
        if (it + 1 < nit) {
            const int k0 = (it + 1) << 5;
#pragma unroll
            for (int u = 0; u < 2; ++u) {
                if (aOk) {
                    float4 v0 = *(const float4*)(Ap + k0 + u * 8);
                    float4 v1 = *(const float4*)(Ap + k0 + u * 8 + 4);
                    ra[u*8+0]=v0.x; ra[u*8+1]=v0.y; ra[u*8+2]=v0.z; ra[u*8+3]=v0.w;
                    ra[u*8+4]=v1.x; ra[u*8+5]=v1.y; ra[u*8+6]=v1.z; ra[u*8+7]=v1.w;
                } else {
#pragma unroll
                    for (int q = 0; q < 8; q++) ra[u*8+q] = 0.f;
                }
                float4 w0 = *(const float4*)(Wp + k0 + u * 8);
                float4 w1 = *(const float4*)(Wp + k0 + u * 8 + 4);
                rb[u*8+0]=w0.x; rb[u*8+1]=w0.y; rb[u*8+2]=w0.z; rb[u*8+3]=w0.w;
                rb[u*8+4]=w1.x; rb[u*8+5]=w1.y; rb[u*8+6]=w1.z; rb[u*8+7]=w1.w;
            }
        }

        const uint32_t stb = sb + (uint32_t)(it & 1) * STAGE;
#pragma unroll
        for (int ks = 0; ks < 2; ++ks) {
            const int kk = ks * 16;
            uint32_t ah[2][4], al[2][4];
#pragma unroll
            for (int mt = 0; mt < 2; ++mt) {
                uint32_t off = (uint32_t)(wm + mt * 16 + (lane & 15)) * 64u
                             + (uint32_t)(kk + (lane >> 4) * 8) * 2u;
                uint32_t sw = SW128(off);
                LDSM_X4(ah[mt][0], ah[mt][1], ah[mt][2], ah[mt][3], stb + T_AH + sw);
                LDSM_X4(al[mt][0], al[mt][1], al[mt][2], al[mt][3], stb + T_AL + sw);
            }
            uint32_t bh_[8][2], bl_[8][2];
#pragma unroll
            for (int nt = 0; nt < 8; ++nt) {
                const int l8 = lane & 15;
                uint32_t boff = (uint32_t)(wn + nt * 8 + (l8 & 7)) * 64u
                              + (uint32_t)(kk + ((l8 >> 3) & 1) * 8) * 2u;
                uint32_t bsw = SW128(boff);
                LDSM_X2(bh_[nt][0], bh_[nt][1], stb + T_BH + bsw);
                LDSM_X2(bl_[nt][0], bl_[nt][1], stb + T_BL + bsw);
            }
            // term-major order: consecutive MMAs hit different accumulators
#pragma unroll
            for (int nt = 0; nt < 8; ++nt) {
                MMA16816(acc[0][nt], ah[0], bh_[nt][0], bh_[nt][1]);
                MMA16816(acc[1][nt], ah[1], bh_[nt][0], bh_[nt][1]);
            }
#pragma unroll
            for (int nt = 0; nt < 8; ++nt) {
                MMA16816(acc[0][nt], ah[0], bl_[nt][0], bl_[nt][1]);
                MMA16816(acc[1][nt], ah[1], bl_[nt][0], bl_[nt][1]);
            }
#pragma unroll
            for (int nt = 0; nt < 8; ++nt) {
                MMA16816(acc[0][nt], al[0], bh_[nt][0], bh_[nt][1]);
                MMA16816(acc[1][nt], al[1], bh_[nt][0], bh_[nt][1]);
            }
        }

        if (it + 1 < nit) {
            const uint32_t base = (uint32_t)((it + 1) & 1) * STAGE;
            const uint32_t soff = lr * 64u;
#pragma unroll
            for (int u = 0; u < 2; ++u) {
                uint32_t off = soff + (uint32_t)(lk + u * 8) * 2u;
                uint32_t sw = SW128(off);
                uint4 hq, lq;
                cvt_hilo8(&ra[u * 8], hq, lq);
                *(uint4*)(smem + base + T_AH + sw) = hq;
                *(uint4*)(smem + base + T_AL + sw) = lq;
                cvt_hilo8(&rb[u * 8], hq, lq);
                *(uint4*)(smem + base + T_BH + sw) = hq;
                *(uint4*)(smem + base + T_BL + sw) = lq;
            }
        }
        __syncthreads();
    }

#pragma unroll
    for (int mt = 0; mt < 2; ++mt) {
#pragma unroll
        for (int half = 0; half < 2; ++half) {
            const int row = bm + wm + mt * 16 + (lane >> 2) + half * 8;
            if (row < M) {
#pragma unroll
                for (int nt = 0; nt < 8; ++nt) {
                    const int col = bn + wn + nt * 8 + (lane & 3) * 2;
                    float v0 = acc[mt][nt][half * 2 + 0];
                    float v1 = acc[mt][nt][half * 2 + 1];
                    if (bias) { v0 += bias[col]; v1 += bias[col + 1]; }
                    if (ACT == 1) {
                        v0 = 0.5f * v0 * (1.0f + erff(v0 * 0.70710678118654752f));
                        v1 = 0.5f * v1 * (1.0f + erff(v1 * 0.70710678118654752f));
                    }
                    *(float2*)&Cmat[(size_t)row * Nn + col] = make_float2(v0, v1);
                }
            }
        }
    }
}

// ================= fused flash attention (tf32 mma, 256 thr) =================
// One CTA = one (b,h) x 64 q-rows. K/V resident in smem, pre-converted to tf32.
// 8 warps: (wq = wid&3) selects 16 q-rows, (wk = wid>>2) splits keys (ph1) / d (ph3).
constexpr int FA_NK  = 264;
constexpr int FA_KST = 68;    // Q/K stride  (68 % 32 == 4  -> conflict-free)
constexpr int FA_SST = 268;   // S/Vt stride (268 % 32 == 12 -> conflict-free)
constexpr int FA_OFF_Q = 0;                          // 64 x 68 (tf32 bits)
constexpr int FA_OFF_K = 64 * FA_KST;                // 264 x 68 (Vt 64 x 268 overlays)
constexpr int FA_OFF_S = FA_OFF_K + FA_NK * FA_KST;  // 64 x 268 (f32)
constexpr int FA_FLOATS = FA_OFF_S + 64 * FA_SST;
constexpr int FATT_SMEM = FA_FLOATS * 4;             // 157,824 B

template<int WRITE_P>
__global__ __launch_bounds__(256, 1)
void k_fattn(const float* __restrict__ qsrc, int qs,
             const float* __restrict__ kvsrc, int kvs, int koff, int voff,
             float* __restrict__ o, float* __restrict__ pout) {
    extern __shared__ __align__(16) float fs[];
    uint32_t* Qs = (uint32_t*)(fs + FA_OFF_Q);
    uint32_t* Ks = (uint32_t*)(fs + FA_OFF_K);
    float*    Ss = fs + FA_OFF_S;

    const int q0 = blockIdx.x * 64;
    const int bh = blockIdx.y;
    const int b = bh / H_, h = bh % H_;
    const int tid = threadIdx.x;
    const int wid = tid >> 5;
    const int lane = tid & 31;
    const int gid = lane >> 2;
    const int tig = lane & 3;
    const int wq = wid & 3;
    const int wk = wid >> 2;
    const int r0 = wq * 16;

    const float* Qg = qsrc + (size_t)b * N_ * qs + h * D_;
    const float* Kg = kvsrc + (size_t)b * N_ * kvs + koff + h * D_;
    const float* Vg = kvsrc + (size_t)b * N_ * kvs + voff + h * D_;

    // ---- load + convert Q (64x64) and K (264x64) to tf32 bits ----
    for (int idx = tid; idx < 64 * 64; idx += 256) {
        int r = idx >> 6, d = idx & 63;
        int q = q0 + r;
        Qs[r * FA_KST + d] = (q < N_) ? f2tf(Qg[(size_t)q * qs + d]) : 0u;
    }
    for (int idx = tid; idx < FA_NK * 64; idx += 256) {
        int r = idx >> 6, d = idx & 63;
        Ks[r * FA_KST + d] = (r < N_) ? f2tf(Kg[(size_t)r * kvs + d]) : 0u;
    }
    __syncthreads();

    // ---- phase 1: S = 0.125 * Q K^T ----
    {
        uint32_t a[8][4];
#pragma unroll
        for (int ks = 0; ks < 8; ++ks) {
            a[ks][0] = Qs[(r0 + gid)     * FA_KST + ks * 8 + tig];
            a[ks][1] = Qs[(r0 + gid + 8) * FA_KST + ks * 8 + tig];
            a[ks][2] = Qs[(r0 + gid)     * FA_KST + ks * 8 + 4 + tig];
            a[ks][3] = Qs[(r0 + gid + 8) * FA_KST + ks * 8 + 4 + tig];
        }
        const int nt0 = wk ? 16 : 0;
        const int nt1 = wk ? 33 : 16;
        int g = nt0;
        for (; g + 4 <= nt1; g += 4) {
            float c[4][4];
#pragma unroll
            for (int j = 0; j < 4; ++j)
#pragma unroll
                for (int r = 0; r < 4; ++r) c[j][r] = 0.f;
#pragma unroll
            for (int ks = 0; ks < 8; ++ks) {
#pragma unroll
                for (int j = 0; j < 4; ++j) {
                    uint32_t b0 = Ks[((g + j) * 8 + gid) * FA_KST + ks * 8 + tig];
                    uint32_t b1 = Ks[((g + j) * 8 + gid) * FA_KST + ks * 8 + 4 + tig];
                    MMA_TF32(c[j], a[ks], b0, b1);
                }
            }
#pragma unroll
            for (int j = 0; j < 4; ++j) {
                Ss[(r0 + gid)     * FA_SST + (g + j) * 8 + tig * 2]     = c[j][0] * 0.125f;
                Ss[(r0 + gid)     * FA_SST + (g + j) * 8 + tig * 2 + 1] = c[j][1] * 0.125f;
                Ss[(r0 + gid + 8) * FA_SST + (g + j) * 8 + tig * 2]     = c[j][2] * 0.125f;
                Ss[(r0 + gid + 8) * FA_SST + (g + j) * 8 + tig * 2 + 1] = c[j][3] * 0.125f;
            }
        }
        for (; g < nt1; ++g) {
            float c[4] = {0.f, 0.f, 0.f, 0.f};
#pragma unroll
            for (int ks = 0; ks < 8; ++ks) {
                uint32_t b0 = Ks[(g * 8 + gid) * FA_KST + ks * 8 + tig];
                uint32_t b1 = Ks[(g * 8 + gid) * FA_KST + ks * 8 + 4 + tig];
                MMA_TF32(c, a[ks], b0, b1);
            }
            Ss[(r0 + gid)     * FA_SST + g * 8 + tig * 2]     = c[0] * 0.125f;
            Ss[(r0 + gid)     * FA_SST + g * 8 + tig * 2 + 1] = c[1] * 0.125f;
            Ss[(r0 + gid + 8) * FA_SST + g * 8 + tig * 2]     = c[2] * 0.125f;
            Ss[(r0 + gid + 8) * FA_SST + g * 8 + tig * 2 + 1] = c[3] * 0.125f;
        }
    }
    __syncthreads();

    // ---- phase 2: softmax (8 rows per warp) ----
#pragma unroll 1
    for (int rr = 0; rr < 8; ++rr) {
        const int row = wid * 8 + rr;
        const int q = q0 + row;
        if (q >= N_) continue;
        float* Sr = Ss + (size_t)row * FA_SST;
        float m = -1e30f;
        for (int c = lane; c < N_; c += 32) m = fmaxf(m, Sr[c]);
#pragma unroll
        for (int off = 16; off > 0; off >>= 1)
            m = fmaxf(m, __shfl_xor_sync(0xFFFFFFFF, m, off));
        float sum = 0.f;
        for (int c = lane; c < N_; c += 32) {
            float e = expf(Sr[c] - m);
            Sr[c] = e;
            sum += e;
        }
#pragma unroll
        for (int off = 16; off > 0; off >>= 1)
            sum += __shfl_xor_sync(0xFFFFFFFF, sum, off);
        const float inv = 1.0f / sum;
        for (int c = lane; c < FA_NK; c += 32) {
            float p = (c < N_) ? Sr[c] * inv : 0.f;
            Sr[c] = p;
            if (WRITE_P && c < N_)
                pout[(size_t)bh * N_ * N_ + (size_t)q * N_ + c] = p;
        }
    }
    __syncthreads();

    // ---- phase 3: Vt load (tf32), O = P V (2-term split on P) ----
    uint32_t* Vt = Ks;
    for (int idx = tid; idx < FA_NK * 64; idx += 256) {
        int key = idx >> 6, d = idx & 63;
        Vt[d * FA_SST + key] = (key < N_) ? f2tf(Vg[(size_t)key * kvs + d]) : 0u;
    }
    __syncthreads();

    float oa[4][4];
#pragma unroll
    for (int nt = 0; nt < 4; ++nt)
#pragma unroll
        for (int r = 0; r < 4; ++r) oa[nt][r] = 0.f;

#pragma unroll 1
    for (int ks = 0; ks < 33; ++ks) {
        float p0 = Ss[(r0 + gid)     * FA_SST + ks * 8 + tig];
        float p1 = Ss[(r0 + gid + 8) * FA_SST + ks * 8 + tig];
        float p2 = Ss[(r0 + gid)     * FA_SST + ks * 8 + 4 + tig];
        float p3 = Ss[(r0 + gid + 8) * FA_SST + ks * 8 + 4 + tig];
        uint32_t ah[4], al[4];
        ah[0] = f2tf(p0); al[0] = __float_as_uint(p0 - __uint_as_float(ah[0]));
        ah[1] = f2tf(p1); al[1] = __float_as_uint(p1 - __uint_as_float(ah[1]));
        ah[2] = f2tf(p2); al[2] = __float_as_uint(p2 - __uint_as_float(ah[2]));
        ah[3] = f2tf(p3); al[3] = __float_as_uint(p3 - __uint_as_float(ah[3]));
        uint32_t vb[4][2];
#pragma unroll
        for (int nt = 0; nt < 4; ++nt) {
            vb[nt][0] = Vt[(wk * 32 + nt * 8 + gid) * FA_SST + ks * 8 + tig];
            vb[nt][1] = Vt[(wk * 32 + nt * 8 + gid) * FA_SST + ks * 8 + 4 + tig];
        }
#pragma unroll
        for (int nt = 0; nt < 4; ++nt) MMA_TF32(oa[nt], ah, vb[nt][0], vb[nt][1]);
#pragma unroll
        for (int nt = 0; nt < 4; ++nt) MMA_TF32(oa[nt], al, vb[nt][0], vb[nt][1]);
    }

    // ---- write O ----
    {
        const int q_a = q0 + r0 + gid;
        const int q_b = q_a + 8;
#pragma unroll
        for (int nt = 0; nt < 4; ++nt) {
            const int col = h * D_ + wk * 32 + nt * 8 + tig * 2;
            if (q_a < N_)
                *(float2*)&o[((size_t)(b * N_ + q_a)) * C_ + col] =
                    make_float2(oa[nt][0], oa[nt][1]);
            if (q_b < N_)
                *(float2*)&o[((size_t)(b * N_ + q_b)) * C_ + col] =
                    make_float2(oa[nt][2], oa[nt][3]);
        }
    }
}

// ---------------- elementwise kernels ----------------
__global__ void k_init(const float* __restrict__ src, const float* __restrict__ tgt,
                       const float* __restrict__ pos, float* __restrict__ s,
                       float* __restrict__ t) {
    size_t i = (size_t)blockIdx.x * blockDim.x + threadIdx.x;
    if (i >= SZ_BNC) return;
    size_t nc = i % ((size_t)N_ * C_);
    s[i] = src[i] + pos[nc];
    t[i] = tgt[i];
}

__global__ void k_add_inplace(float* __restrict__ y, const float* __restrict__ x, size_t n) {
    size_t i = (size_t)blockIdx.x * blockDim.x + threadIdx.x;
    if (i < n) y[i] += x[i];
}

__global__ void k_add_out(const float* __restrict__ a, const float* __restrict__ b,
                          float* __restrict__ out, size_t n) {
    size_t i = (size_t)blockIdx.x * blockDim.x + threadIdx.x;
    if (i < n) out[i] = a[i] + b[i];
}

__global__ void k_arf(float* __restrict__ x, size_t n) {
    size_t i = (size_t)blockIdx.x * blockDim.x + threadIdx.x;
    if (i >= n) return;
    float v = x[i];
    float ep = expf(v), en = expf(-v), en4 = expf(-v - 4.0f);
    float tmp = (ep - en) / (ep + en4);
    x[i] = tmp < 0.0f ? 0.0f : tmp;
}

// ---------------- layernorm ----------------
__global__ void k_ln(const float* __restrict__ x, const float* __restrict__ g,
                     const float* __restrict__ b, float* __restrict__ y) {
    int row = blockIdx.x;
    int tid = threadIdx.x;
    const float* xr = x + (size_t)row * C_;
    float s = 0.f, q = 0.f;
    for (int i = tid; i < C_; i += 256) { float v = xr[i]; s += v; q += v * v; }
    __shared__ float rs[256], rq[256];
    rs[tid] = s; rq[tid] = q; __syncthreads();
    for (int o = 128; o > 0; o >>= 1) {
        if (tid < o) { rs[tid] += rs[tid + o]; rq[tid] += rq[tid + o]; }
        __syncthreads();
    }
    float mean = rs[0] * (1.0f / C_);
    float var  = rq[0] * (1.0f / C_) - mean * mean;
    float inv  = rsqrtf(var + 1e-5f);
    float* yr = y + (size_t)row * C_;
    for (int i = tid; i < C_; i += 256)
        yr[i] = (xr[i] - mean) * inv * g[i] + b[i];
}

// ---------------- head sum ----------------
__global__ void k_headsum(const float* __restrict__ attn, float* __restrict__ asum) {
    size_t idx = (size_t)blockIdx.x * 256 + threadIdx.x;
    if (idx >= SZ_ASUM) return;
    size_t b = idx / ((size_t)N_ * N_);
    size_t r = idx % ((size_t)N_ * N_);
    float s = 0.f;
    for (int h = 0; h < H_; h++) s += attn[((size_t)(b * H_ + h)) * N_ * N_ + r];
    asum[idx] = s;
}

// ---------------- heat ----------------
__global__ void k_heat(const float* __restrict__ asum, float* __restrict__ heat) {
    int idx = blockIdx.x * 256 + threadIdx.x;
    if (idx >= B_ * N_) return;
    int b = idx / N_, m = idx % N_;
    const float* p = asum + (size_t)b * N_ * N_ + m;
    float s = 0.f;
    for (int n = 0; n < N_; n++) s += p[(size_t)n * N_];
    heat[idx] = s * (1.0f / N_);
}

// ---------------- tgt output ----------------
__global__ void k_tgt_out(const float* __restrict__ t, const float* __restrict__ saw,
                          const float* __restrict__ heat, float* __restrict__ out) {
    size_t i = (size_t)blockIdx.x * 256 + threadIdx.x;
    if (i >= SZ_BNC) return;
    int row = (int)(i / C_);
    int c   = (int)(i % C_);
    float gate = 1.0f / (1.0f + expf(-heat[row]));
    float tv = t[i];
    out[i] = tv + tv * saw[c] * gate;
}

// ---------------- attm copy ----------------
__global__ void k_attm(const float* __restrict__ asum, float* __restrict__ out) {
    size_t idx = (size_t)blockIdx.x * 256 + threadIdx.x;
    size_t total = (size_t)B_ * 256 * 256;
    if (idx >= total) return;
    size_t b = idx / 65536;
    size_t r = idx % 65536;
    int i = (int)(r >> 8), j = (int)(r & 255);
    out[idx] = asum[(size_t)b * N_ * N_ + (size_t)(i + 1) * N_ + (j + 1)];
}

// ---------------- host orchestration ----------------
static inline dim3 tc_grid(int Nn) { return dim3(Nn / 128, (M_ + 127) / 128); }

extern "C" void kernel_launch(void* const* d_in, const int* in_sizes, int n_in,
                              void* d_out, int out_size) {
    const float* in_src   = (const float*)d_in[0];
    const float* in_tgt   = (const float*)d_in[1];
    const float* sattn_qkv_w  = (const float*)d_in[2];
    const float* sattn_proj_w = (const float*)d_in[3];
    const float* sattn_proj_b = (const float*)d_in[4];
    const float* cattn_qkv_w  = (const float*)d_in[5];
    const float* cattn_proj_w = (const float*)d_in[6];
    const float* cattn_proj_b = (const float*)d_in[7];
    const float* n1g = (const float*)d_in[8];
    const float* n1b = (const float*)d_in[9];
    const float* n2g = (const float*)d_in[10];
    const float* n2b = (const float*)d_in[11];
    const float* fc1_w = (const float*)d_in[12];
    const float* fc1_b = (const float*)d_in[13];
    const float* fc2_w = (const float*)d_in[14];
    const float* fc2_b = (const float*)d_in[15];
    const float* saw   = (const float*)d_in[16];
    const float* pos   = (const float*)d_in[17];

    float *s, *t, *ln, *q1, *q2, *at, *ob, *sc, *hd, *tp, *as_, *ht;
    cudaGetSymbolAddress((void**)&s,   g_s);
    cudaGetSymbolAddress((void**)&t,   g_t);
    cudaGetSymbolAddress((void**)&ln,  g_ln);
    cudaGetSymbolAddress((void**)&q1,  g_q1);
    cudaGetSymbolAddress((void**)&q2,  g_q2);
    cudaGetSymbolAddress((void**)&at,  g_att);
    cudaGetSymbolAddress((void**)&ob,  g_o);
    cudaGetSymbolAddress((void**)&sc,  g_sc);
    cudaGetSymbolAddress((void**)&hd,  g_hid);
    cudaGetSymbolAddress((void**)&tp,  g_tmp);
    cudaGetSymbolAddress((void**)&as_, g_asum);
    cudaGetSymbolAddress((void**)&ht,  g_heat);

    cudaFuncSetAttribute((const void*)gemm_mma<0>,
                         cudaFuncAttributeMaxDynamicSharedMemorySize, GEMM_SMEM);
    cudaFuncSetAttribute((const void*)gemm_mma<1>,
                         cudaFuncAttributeMaxDynamicSharedMemorySize, GEMM_SMEM);
    cudaFuncSetAttribute((const void*)k_fattn<0>,
                         cudaFuncAttributeMaxDynamicSharedMemorySize, FATT_SMEM);
    cudaFuncSetAttribute((const void*)k_fattn<1>,
                         cudaFuncAttributeMaxDynamicSharedMemorySize, FATT_SMEM);

    float* out_src  = (float*)d_out;
    float* out_tgt  = out_src + SZ_BNC;
    float* out_attm = out_tgt + SZ_BNC;

    const int EW = (int)((SZ_BNC + 255) / 256);
    dim3 fa_grid((N_ + 63) / 64, B_ * H_);

    // ---- src = src + pos; t = tgt ----
    k_init<<<EW, 256>>>(in_src, in_tgt, pos, s, t);

    // ---- self attention on src ----
    k_ln<<<M_, 256>>>(s, n1g, n1b, ln);
    gemm_mma<0><<<tc_grid(C3_), 256, GEMM_SMEM>>>(ln, sattn_qkv_w, nullptr, q1, M_, C3_, C_);
    k_fattn<0><<<fa_grid, 256, FATT_SMEM>>>(q1, C3_, q1, C3_, C_, 2 * C_, ob, nullptr);
    gemm_mma<0><<<tc_grid(C_), 256, GEMM_SMEM>>>(ob, sattn_proj_w, sattn_proj_b, sc, M_, C_, C_);
    k_add_inplace<<<EW, 256>>>(s, sc, SZ_BNC);
    k_ln<<<M_, 256>>>(sc, n2g, n2b, ln);
    gemm_mma<1><<<tc_grid(HID_), 256, GEMM_SMEM>>>(ln, fc1_w, fc1_b, hd, M_, HID_, C_);
    gemm_mma<0><<<tc_grid(C_), 256, GEMM_SMEM>>>(hd, fc2_w, fc2_b, tp, M_, C_, HID_);
    k_add_inplace<<<EW, 256>>>(s, tp, SZ_BNC);

    // ---- self attention on tgt ----
    k_ln<<<M_, 256>>>(t, n1g, n1b, ln);
    gemm_mma<0><<<tc_grid(C3_), 256, GEMM_SMEM>>>(ln, sattn_qkv_w, nullptr, q1, M_, C3_, C_);
    k_fattn<0><<<fa_grid, 256, FATT_SMEM>>>(q1, C3_, q1, C3_, C_, 2 * C_, ob, nullptr);
    gemm_mma<0><<<tc_grid(C_), 256, GEMM_SMEM>>>(ob, sattn_proj_w, sattn_proj_b, sc, M_, C_, C_);
    k_add_inplace<<<EW, 256>>>(t, sc, SZ_BNC);
    k_ln<<<M_, 256>>>(sc, n2g, n2b, ln);
    gemm_mma<1><<<tc_grid(HID_), 256, GEMM_SMEM>>>(ln, fc1_w, fc1_b, hd, M_, HID_, C_);
    gemm_mma<0><<<tc_grid(C_), 256, GEMM_SMEM>>>(hd, fc2_w, fc2_b, tp, M_, C_, HID_);
    k_add_inplace<<<EW, 256>>>(t, tp, SZ_BNC);

    // ---- cross attention (Q-only GEMM for src, KV-only for tgt) ----
    k_ln<<<M_, 256>>>(s, n1g, n1b, ln);
    gemm_mma<0><<<tc_grid(C_), 256, GEMM_SMEM>>>(ln, cattn_qkv_w, nullptr, q1, M_, C_, C_);
    k_ln<<<M_, 256>>>(t, n1g, n1b, ln);
    gemm_mma<0><<<tc_grid(2 * C_), 256, GEMM_SMEM>>>(ln, cattn_qkv_w + (size_t)C_ * C_,
                                                     nullptr, q2, M_, 2 * C_, C_);
    k_fattn<1><<<fa_grid, 256, FATT_SMEM>>>(q1, C_, q2, 2 * C_, 0, C_, ob, at);
    k_headsum<<<(int)((SZ_ASUM + 255) / 256), 256>>>(at, as_);
    gemm_mma<0><<<tc_grid(C_), 256, GEMM_SMEM>>>(ob, cattn_proj_w, cattn_proj_b, sc, M_, C_, C_);
    k_arf<<<EW, 256>>>(sc, SZ_BNC);
    k_add_inplace<<<EW, 256>>>(s, sc, SZ_BNC);
    k_ln<<<M_, 256>>>(sc, n2g, n2b, ln);
    gemm_mma<1><<<tc_grid(HID_), 256, GEMM_SMEM>>>(ln, fc1_w, fc1_b, hd, M_, HID_, C_);
    gemm_mma<0><<<tc_grid(C_), 256, GEMM_SMEM>>>(hd, fc2_w, fc2_b, tp, M_, C_, HID_);
    k_add_out<<<EW, 256>>>(s, tp, out_src, SZ_BNC);

    // ---- gate + tgt out ----
    k_heat<<<(B_ * N_ + 255) / 256, 256>>>(as_, ht);
    k_tgt_out<<<EW, 256>>>(t, saw, ht, out_tgt);

    // ---- attm out ----
    k_attm<<<(int)(((size_t)B_ * 256 * 256 + 255) / 256), 256>>>(as_, out_attm);
}